// round 11
// baseline (speedup 1.0000x reference)
#include <cuda_runtime.h>
#include <cuda_bf16.h>
#include <math.h>

#define N_NODES 4096
#define H_DIM   128
#define NEGV    (-1000000000.0f)
#define GAT_SPLITS 16
#define J_PER_SPLIT (N_NODES / GAT_SPLITS)   // 256 -> 8 tiles of 32
#define WT_STR 132

// ---------------- device scratch (no allocations allowed) ----------------
__device__ float g_s1[N_NODES];
__device__ float g_d1[N_NODES];
__device__ float g_g1[N_NODES * H_DIM];
__device__ float g_s2[N_NODES];
__device__ float g_d2[N_NODES];
__device__ float g_hn[N_NODES * H_DIM];
__device__ unsigned g_h1b[N_NODES * H_DIM / 2];   // bf16x2 packed h1
__device__ unsigned g_h2b[N_NODES * H_DIM / 2];   // bf16x2 packed h2
__device__ unsigned g_qb [N_NODES * H_DIM / 2];   // bf16x2 packed q
__device__ float g_part[GAT_SPLITS * N_NODES * H_DIM];
__device__ float g_zp [GAT_SPLITS * N_NODES];
__device__ int   g_cnt[N_NODES / 32];             // last-arriver counters (0-init)

// ---- fast gelu: tanh-approx via MUFU.TANH ----
__device__ __forceinline__ float tanh_fast(float y) {
    float r;
    asm("tanh.approx.f32 %0, %1;" : "=f"(r) : "f"(y));
    return r;
}
__device__ __forceinline__ float gelu_fast(float x) {
    float x2 = x * x;
    float inner = x * fmaf(0.0356774081f, x2, 0.79788456080f);
    float hx = 0.5f * x;
    return fmaf(hx, tanh_fast(inner), hx);
}

// ---- packed fp32x2 FMA ----
__device__ __forceinline__ unsigned long long ffma2(unsigned long long a,
                                                    unsigned long long b,
                                                    unsigned long long c) {
    unsigned long long d;
    asm("fma.rn.f32x2 %0, %1, %2, %3;" : "=l"(d) : "l"(a), "l"(b), "l"(c));
    return d;
}
__device__ __forceinline__ unsigned long long pack2(float x, float y) {
    unsigned long long d;
    asm("mov.b64 %0, {%1, %2};" : "=l"(d) : "f"(x), "f"(y));
    return d;
}
__device__ __forceinline__ float2 unpack2(unsigned long long v) {
    float2 r;
    asm("mov.b64 {%0, %1}, %2;" : "=f"(r.x), "=f"(r.y) : "l"(v));
    return r;
}

// ---- bf16 helpers ----
__device__ __forceinline__ unsigned bf16x2_of(float lo, float hi) {
    unsigned r;
    asm("cvt.rn.bf16x2.f32 %0, %1, %2;" : "=r"(r) : "f"(hi), "f"(lo));
    return r;
}
__device__ __forceinline__ unsigned mul_bf16x2(unsigned a, unsigned b) {
    unsigned r;
    asm("mul.bf16x2 %0, %1, %2;" : "=r"(r) : "r"(a), "r"(b));
    return r;
}
__device__ __forceinline__ void mma16816(float* c, const unsigned* a,
                                         unsigned b0, unsigned b1) {
    asm("mma.sync.aligned.m16n8k16.row.col.f32.bf16.bf16.f32 "
        "{%0,%1,%2,%3}, {%4,%5,%6,%7}, {%8,%9}, {%0,%1,%2,%3};"
        : "+f"(c[0]), "+f"(c[1]), "+f"(c[2]), "+f"(c[3])
        : "r"(a[0]), "r"(a[1]), "r"(a[2]), "r"(a[3]), "r"(b0), "r"(b1));
}
__device__ __forceinline__ void ldsm_x4_t(unsigned& r0, unsigned& r1,
                                          unsigned& r2, unsigned& r3,
                                          unsigned addr) {
    asm volatile("ldmatrix.sync.aligned.m8n8.x4.trans.shared.b16 "
                 "{%0,%1,%2,%3}, [%4];"
                 : "=r"(r0), "=r"(r1), "=r"(r2), "=r"(r3) : "r"(addr));
}
__device__ __forceinline__ void ldsm_x4(unsigned& r0, unsigned& r1,
                                        unsigned& r2, unsigned& r3,
                                        unsigned addr) {
    asm volatile("ldmatrix.sync.aligned.m8n8.x4.shared.b16 "
                 "{%0,%1,%2,%3}, [%4];"
                 : "=r"(r0), "=r"(r1), "=r"(r2), "=r"(r3) : "r"(addr));
}
__device__ __forceinline__ unsigned smem_u32(const void* p) {
    return (unsigned)__cvta_generic_to_shared(p);
}

// =========================================================================
// GEMM: h = in[4096][K] @ W[128][K]^T (+bias) -> packed bf16; 16-row tiles
// (grid 256 -> 2 CTAs/SM for latency overlap). Optionally s/d scalars.
// =========================================================================
__global__ void gemm_attn_kernel(const float* __restrict__ in, int K,
                                 const float* __restrict__ W,
                                 const float* __restrict__ a_s,
                                 const float* __restrict__ a_d,
                                 const float* __restrict__ bias,
                                 unsigned* __restrict__ out_bf,
                                 float* __restrict__ s_out,
                                 float* __restrict__ d_out) {
    extern __shared__ float sm[];
    float* in_s = sm;            // 16*K
    float* Wt   = sm + 16 * K;   // K rows of WT_STR
    const int tid = threadIdx.x;
    const int i0  = blockIdx.x * 16;

    {   // rows contiguous -> straight float4 copy (16 rows)
        const float4* gin4 = reinterpret_cast<const float4*>(in + (size_t)i0 * K);
        float4* in4 = reinterpret_cast<float4*>(in_s);
        for (int idx = tid; idx < 4 * K; idx += 256) in4[idx] = gin4[idx];
    }
    for (int idx = tid; idx < 128 * K; idx += 256) {
        int c = idx / K, k = idx - c * K;
        Wt[k * WT_STR + c] = W[idx];
    }
    __syncthreads();

    const int rg = tid >> 5;        // warp handles rows rg*2, rg*2+1
    const int lane = tid & 31;
    unsigned long long acc2[2][2];
#pragma unroll
    for (int r = 0; r < 2; ++r) { acc2[r][0] = 0ull; acc2[r][1] = 0ull; }

    for (int k = 0; k < K; ++k) {
        longlong2 B = *reinterpret_cast<const longlong2*>(&Wt[k * WT_STR + lane * 4]);
#pragma unroll
        for (int rr = 0; rr < 2; ++rr) {
            float a = in_s[(rg * 2 + rr) * K + k];
            unsigned long long aa = pack2(a, a);
            acc2[rr][0] = ffma2(aa, (unsigned long long)B.x, acc2[rr][0]);
            acc2[rr][1] = ffma2(aa, (unsigned long long)B.y, acc2[rr][1]);
        }
    }

    float acc[2][4];
#pragma unroll
    for (int rr = 0; rr < 2; ++rr) {
        float2 p0 = unpack2(acc2[rr][0]);
        float2 p1 = unpack2(acc2[rr][1]);
        acc[rr][0] = p0.x; acc[rr][1] = p0.y; acc[rr][2] = p1.x; acc[rr][3] = p1.y;
    }

#pragma unroll
    for (int rr = 0; rr < 2; ++rr) {
        int row = i0 + rg * 2 + rr;
        float v0 = acc[rr][0], v1 = acc[rr][1], v2 = acc[rr][2], v3 = acc[rr][3];
        if (bias) {
            v0 += bias[lane * 4 + 0];
            v1 += bias[lane * 4 + 1];
            v2 += bias[lane * 4 + 2];
            v3 += bias[lane * 4 + 3];
        }
        uint2 o;
        o.x = bf16x2_of(v0, v1);
        o.y = bf16x2_of(v2, v3);
        *reinterpret_cast<uint2*>(&out_bf[(size_t)row * 64 + lane * 2]) = o;
    }

    if (s_out) {
#pragma unroll
        for (int rr = 0; rr < 2; ++rr) {
            float sp = 0.f, dp = 0.f;
#pragma unroll
            for (int cc = 0; cc < 4; ++cc) {
                int c = lane * 4 + cc;
                sp += acc[rr][cc] * __ldg(&a_s[c]);
                dp += acc[rr][cc] * __ldg(&a_d[c]);
            }
#pragma unroll
            for (int off = 16; off; off >>= 1) {
                sp += __shfl_xor_sync(0xffffffffu, sp, off);
                dp += __shfl_xor_sync(0xffffffffu, dp, off);
            }
            if (lane == 0) {
                s_out[i0 + rg * 2 + rr] = sp;
                d_out[i0 + rg * 2 + rr] = dp;
            }
        }
    }
}

// =========================================================================
// GAT split-K partial + FUSED last-arriver reduce.
// Grid (128 i-tiles x 16 splits). Each CTA computes its partial; the last
// CTA to finish an i-tile (threadfence + atomic counter) sums the 16
// partials IN FIXED INDEX ORDER (deterministic) and runs the epilogue
// (1/Z, relu, +res, LayerNorm). Counter self-resets for graph replay.
// =========================================================================
#define GB_H0 0
#define GB_H1 8704
#define GB_W0 17408
#define GB_W1 19968
#define GB_TOTAL 22528

__global__ void __launch_bounds__(256, 3)
gat_part_kernel(const unsigned* __restrict__ hb,
                const float* __restrict__ s,
                const float* __restrict__ d,
                const int*   __restrict__ adj,
                float* __restrict__ part,
                float* __restrict__ zp,
                const float* __restrict__ res,
                const float* __restrict__ lnw,
                const float* __restrict__ lnb,
                float* __restrict__ outp,
                int do_ln,
                int* __restrict__ cnt) {
    __shared__ __align__(16) char smraw[GB_TOTAL];
    __shared__ float z_s[32];
    __shared__ int is_last;
    __nv_bfloat16* h_sb[2] = { (__nv_bfloat16*)(smraw + GB_H0),
                               (__nv_bfloat16*)(smraw + GB_H1) };
    __nv_bfloat16* w_sb[2] = { (__nv_bfloat16*)(smraw + GB_W0),
                               (__nv_bfloat16*)(smraw + GB_W1) };

    const int tid = threadIdx.x;
    const int i0  = blockIdx.x * 32;
    const int sz  = blockIdx.y;
    const int jb  = sz * J_PER_SPLIT;

    const int lane = tid & 31;
    const int w    = tid >> 5;
    const int rg   = w;
    const int wi   = tid >> 3;
    const int wj   = (tid & 7) * 4;
    const float si = s[i0 + wi];

    const int fg = lane >> 2, ft = lane & 3;
    const int m0 = (w & 1) * 16;
    const int n0 = (w >> 1) * 32;
    const int lm_ti = lane >> 3, lm_r = lane & 7;
    const int lm_off = ((lm_ti & 1) * 8 + lm_r) * 136 + (lm_ti >> 1) * 8;
    const unsigned hb_u32[2] = { smem_u32(h_sb[0]), smem_u32(h_sb[1]) };
    const int aw = (m0 + fg) * 40 + 2 * ft;

    float zacc = 0.f;
    float acc[4][4];
#pragma unroll
    for (int i = 0; i < 4; ++i)
#pragma unroll
        for (int k = 0; k < 4; ++k) acc[i][k] = 0.f;

    int4 av; float4 dv; uint2 hv0, hv1, hv2, hv3;

#define GAT_LOAD(J0)                                                          \
    do {                                                                      \
        av = *reinterpret_cast<const int4*>(                                  \
            &adj[(size_t)(i0 + wi) * N_NODES + (J0) + wj]);                   \
        dv = *reinterpret_cast<const float4*>(&d[(J0) + wj]);                 \
        const uint2* h2p = reinterpret_cast<const uint2*>(hb);                \
        hv0 = h2p[(size_t)((J0) + rg +  0) * 32 + lane];                      \
        hv1 = h2p[(size_t)((J0) + rg +  8) * 32 + lane];                      \
        hv2 = h2p[(size_t)((J0) + rg + 16) * 32 + lane];                      \
        hv3 = h2p[(size_t)((J0) + rg + 24) * 32 + lane];                      \
    } while (0)

#define GAT_STORE(BUF)                                                        \
    do {                                                                      \
        float w0 = 0.f, w1 = 0.f, w2 = 0.f, w3 = 0.f;                         \
        if (av.x > 0) { float e = si + dv.x; e = (e > 0.f) ? e : 0.2f * e; w0 = __expf(e); } \
        if (av.y > 0) { float e = si + dv.y; e = (e > 0.f) ? e : 0.2f * e; w1 = __expf(e); } \
        if (av.z > 0) { float e = si + dv.z; e = (e > 0.f) ? e : 0.2f * e; w2 = __expf(e); } \
        if (av.w > 0) { float e = si + dv.w; e = (e > 0.f) ? e : 0.2f * e; w3 = __expf(e); } \
        zacc += (w0 + w1) + (w2 + w3);                                        \
        uint2 wp; wp.x = bf16x2_of(w0, w1); wp.y = bf16x2_of(w2, w3);         \
        *reinterpret_cast<uint2*>(&w_sb[BUF][wi * 40 + wj]) = wp;             \
        *reinterpret_cast<uint2*>(&h_sb[BUF][(rg +  0) * 136 + lane * 4]) = hv0; \
        *reinterpret_cast<uint2*>(&h_sb[BUF][(rg +  8) * 136 + lane * 4]) = hv1; \
        *reinterpret_cast<uint2*>(&h_sb[BUF][(rg + 16) * 136 + lane * 4]) = hv2; \
        *reinterpret_cast<uint2*>(&h_sb[BUF][(rg + 24) * 136 + lane * 4]) = hv3; \
    } while (0)

    GAT_LOAD(jb);
    GAT_STORE(0);
    __syncthreads();

    int buf = 0;
    const int NT = J_PER_SPLIT / 32;
    for (int t = 0; t < NT; ++t) {
        const int nxt = jb + (t + 1) * 32;
        if (t + 1 < NT) GAT_LOAD(nxt);

        const __nv_bfloat16* wb = w_sb[buf];
        const unsigned hbase = hb_u32[buf] + lm_off * 2;
#pragma unroll
        for (int sstep = 0; sstep < 2; ++sstep) {
            const int k0 = 16 * sstep;
            unsigned A[4];
            A[0] = *reinterpret_cast<const unsigned*>(&wb[aw + k0]);
            A[1] = *reinterpret_cast<const unsigned*>(&wb[aw + 320 + k0]);
            A[2] = *reinterpret_cast<const unsigned*>(&wb[aw + k0 + 8]);
            A[3] = *reinterpret_cast<const unsigned*>(&wb[aw + 320 + k0 + 8]);
#pragma unroll
            for (int p = 0; p < 2; ++p) {
                unsigned r0, r1, r2, r3;
                ldsm_x4_t(r0, r1, r2, r3,
                          hbase + (k0 * 136 + n0 + 16 * p) * 2);
                mma16816(acc[2 * p + 0], A, r0, r1);
                mma16816(acc[2 * p + 1], A, r2, r3);
            }
        }

        if (t + 1 < NT) GAT_STORE(buf ^ 1);
        __syncthreads();
        buf ^= 1;
    }
#undef GAT_LOAD
#undef GAT_STORE

    zacc += __shfl_xor_sync(0xffffffffu, zacc, 4);
    zacc += __shfl_xor_sync(0xffffffffu, zacc, 2);
    zacc += __shfl_xor_sync(0xffffffffu, zacc, 1);
    if ((tid & 7) == 0) zp[(size_t)sz * N_NODES + i0 + wi] = zacc;

    float* pb = &part[((size_t)sz * N_NODES + i0) * 128];
#pragma unroll
    for (int i = 0; i < 4; ++i) {
        const int col = n0 + 8 * i + 2 * ft;
        float2 lo; lo.x = acc[i][0]; lo.y = acc[i][1];
        float2 hi; hi.x = acc[i][2]; hi.y = acc[i][3];
        *reinterpret_cast<float2*>(&pb[(m0 + fg) * 128 + col])     = lo;
        *reinterpret_cast<float2*>(&pb[(m0 + 8 + fg) * 128 + col]) = hi;
    }

    // ---- last-arriver reduce (threadFenceReduction pattern) ----
    __threadfence();
    if (tid == 0) {
        int prev = atomicAdd(&cnt[blockIdx.x], 1);
        is_last = (prev == GAT_SPLITS - 1) ? 1 : 0;
    }
    __syncthreads();
    if (!is_last) return;
    if (tid == 0) cnt[blockIdx.x] = 0;    // reset for next layer / replay

    if (tid < 32) {
        float z = 0.f;
#pragma unroll
        for (int ss = 0; ss < GAT_SPLITS; ++ss)
            z += zp[(size_t)ss * N_NODES + i0 + tid];
        z_s[tid] = z;
    }
    __syncthreads();

#pragma unroll
    for (int rr = 0; rr < 4; ++rr) {
        const int lrow = rg * 4 + rr;
        const int row  = i0 + lrow;
        float4 a = make_float4(0.f, 0.f, 0.f, 0.f);
#pragma unroll
        for (int ss = 0; ss < GAT_SPLITS; ++ss) {
            float4 p = *reinterpret_cast<const float4*>(
                &part[((size_t)ss * N_NODES + row) * 128 + lane * 4]);
            a.x += p.x; a.y += p.y; a.z += p.z; a.w += p.w;
        }
        const float z = z_s[lrow];
        const float zinv = (z > 0.f) ? (1.0f / z) : 0.f;
        float v[4] = {a.x, a.y, a.z, a.w};
#pragma unroll
        for (int cc = 0; cc < 4; ++cc) {
            float t = fmaxf(v[cc] * zinv, 0.f);
            if (res) t += res[(size_t)row * 128 + lane * 4 + cc];
            v[cc] = t;
        }
        if (do_ln) {
            float sum = v[0] + v[1] + v[2] + v[3];
            float sq  = v[0]*v[0] + v[1]*v[1] + v[2]*v[2] + v[3]*v[3];
#pragma unroll
            for (int off = 16; off; off >>= 1) {
                sum += __shfl_xor_sync(0xffffffffu, sum, off);
                sq  += __shfl_xor_sync(0xffffffffu, sq,  off);
            }
            const float mu  = sum * (1.0f / 128.0f);
            const float var = sq  * (1.0f / 128.0f) - mu * mu;
            const float rs  = rsqrtf(var + 1e-5f);
#pragma unroll
            for (int cc = 0; cc < 4; ++cc) {
                int c = lane * 4 + cc;
                v[cc] = (v[cc] - mu) * rs * __ldg(&lnw[c]) + __ldg(&lnb[c]);
            }
        }
        float4 o; o.x = v[0]; o.y = v[1]; o.z = v[2]; o.w = v[3];
        *reinterpret_cast<float4*>(&outp[(size_t)row * 128 + lane * 4]) = o;
    }
}

// =========================================================================
// Candidate head: persistent bf16 MMA (unchanged from R10)
// =========================================================================
#define STR1 136
#define STR3 264

#define OB_WC2  0
#define OB_WS1  34816
#define OB_T1   102400
#define OB_T2   137216
#define OB_WC1T 172032
#define OB_CF   177152
#define OB_QB   182272
#define OB_BC1  182784
#define OB_BC2  183296
#define OB_BS1  183808
#define OB_WS2  184320
#define OB_AM   184832
#define OB_PART 185344
#define OB_MISC 186368
#define CAND_SMEM_BYTES 186400
#define N_PAIRS 2048

__global__ void __launch_bounds__(256, 1)
cand_kernel(const float* __restrict__ cf,
            const float* __restrict__ am,
            const float* __restrict__ Wc1, const float* __restrict__ bc1,
            const float* __restrict__ Wc2, const float* __restrict__ bc2,
            const float* __restrict__ Ws1, const float* __restrict__ bs1,
            const float* __restrict__ Ws2, const float* __restrict__ bs2,
            const unsigned* __restrict__ qbg,
            float* __restrict__ out) {
    extern __shared__ char smc[];
    __nv_bfloat16* Wc2b = (__nv_bfloat16*)(smc + OB_WC2);
    __nv_bfloat16* Ws1b = (__nv_bfloat16*)(smc + OB_WS1);
    __nv_bfloat16* T1b  = (__nv_bfloat16*)(smc + OB_T1);
    __nv_bfloat16* T2b  = (__nv_bfloat16*)(smc + OB_T2);
    float* Wc1t = (float*)(smc + OB_WC1T);
    float* cf_s = (float*)(smc + OB_CF);
    unsigned* qb = (unsigned*)(smc + OB_QB);
    float* bc1s = (float*)(smc + OB_BC1);
    float* bc2s = (float*)(smc + OB_BC2);
    float* bs1s = (float*)(smc + OB_BS1);
    float* Ws2s = (float*)(smc + OB_WS2);
    float* am_s = (float*)(smc + OB_AM);
    float* part = (float*)(smc + OB_PART);
    float* misc = (float*)(smc + OB_MISC);

    const int tid = threadIdx.x;

    for (int i2 = tid; i2 < 8192; i2 += 256) {
        int n = i2 >> 6, kp = i2 & 63;
        float2 v = *reinterpret_cast<const float2*>(&Wc2[n * 128 + 2 * kp]);
        *reinterpret_cast<unsigned*>(&Wc2b[n * STR1 + 2 * kp]) = bf16x2_of(v.x, v.y);
    }
    for (int i2 = tid; i2 < 16384; i2 += 256) {
        int n = i2 >> 7, kp = i2 & 127;
        float2 v = *reinterpret_cast<const float2*>(&Ws1[n * 256 + 2 * kp]);
        *reinterpret_cast<unsigned*>(&Ws1b[n * STR3 + 2 * kp]) = bf16x2_of(v.x, v.y);
    }
    for (int idx = tid; idx < 1280; idx += 256) {
        int c = idx / 10, j = idx - c * 10;
        Wc1t[j * 128 + c] = Wc1[idx];
    }
    if (tid < 128) {
        bc1s[tid] = bc1[tid];
        bc2s[tid] = bc2[tid];
        bs1s[tid] = bs1[tid];
        Ws2s[tid] = Ws2[tid];
    }
    const float bs2v = __ldg(&bs2[0]);

    const int w    = tid >> 5;
    const int lane = tid & 31;
    const int fg   = lane >> 2;
    const int ft   = lane & 3;
    const int wm   = w & 3;
    const int wn   = w >> 2;
    const int m0   = wm * 32;
    const int nc0  = wn * 64;
    const int node = wm >> 1;
    const int rg1  = tid >> 4;
    const int cg1  = tid & 15;

    const int a_row  = ((lane >> 3) & 1) * 8 + (lane & 7);
    const int a_koff = (lane >> 4) * 8;
    const unsigned t1_u32 = smem_u32(T1b);
    const unsigned t2_u32 = smem_u32(T2b);
    const unsigned a1_base0 = t1_u32 + 2 * ((m0 + a_row) * STR1 + a_koff);
    const unsigned a1_base1 = t1_u32 + 2 * ((m0 + 16 + a_row) * STR1 + a_koff);
    const unsigned a2_base0 = t2_u32 + 2 * ((m0 + a_row) * STR1 + a_koff);
    const unsigned a2_base1 = t2_u32 + 2 * ((m0 + 16 + a_row) * STR1 + a_koff);
    const int b_m     = lane >> 3;
    const int b_iloc  = b_m >> 1;
    const int b_koff  = (b_m & 1) * 8;
    const int b_row   = lane & 7;
    const unsigned wc2_u32 = smem_u32(Wc2b);
    const unsigned ws1_u32 = smem_u32(Ws1b);
    unsigned b2_base[4], b3_base[4];
#pragma unroll
    for (int ii = 0; ii < 4; ++ii) {
        int nrow = nc0 + 8 * (2 * ii + b_iloc) + b_row;
        b2_base[ii] = wc2_u32 + 2 * (nrow * STR1 + b_koff);
        b3_base[ii] = ws1_u32 + 2 * (nrow * STR3 + b_koff);
    }

    for (int pr = blockIdx.x; pr < N_PAIRS; pr += gridDim.x) {
        const int n0  = pr * 2;
        const int base_row = n0 * 64;

        __syncthreads();

        for (int idx = tid; idx < 1280; idx += 256)
            cf_s[idx] = cf[(size_t)base_row * 10 + idx];
        if (tid < 128) {
            qb[tid] = qbg[(size_t)n0 * 64 + tid];
            am_s[tid] = am[base_row + tid];
        }
        __syncthreads();

        if (tid < 2) {
            float ssum = 0.f;
            for (int c = 0; c < 64; ++c) ssum += am_s[tid * 64 + c];
            misc[tid] = (ssum <= 0.f) ? 1.f : 0.f;
        }

        // ---- stage 1 ----
        {
            unsigned long long a2[8][4];
#pragma unroll
            for (int r = 0; r < 8; ++r)
#pragma unroll
                for (int c = 0; c < 4; ++c) a2[r][c] = 0ull;
#pragma unroll
            for (int j = 0; j < 10; ++j) {
                longlong2 B0 = *reinterpret_cast<const longlong2*>(&Wc1t[j * 128 + cg1 * 8]);
                longlong2 B1 = *reinterpret_cast<const longlong2*>(&Wc1t[j * 128 + cg1 * 8 + 4]);
#pragma unroll
                for (int rr = 0; rr < 8; ++rr) {
                    float a = cf_s[(rg1 * 8 + rr) * 10 + j];
                    unsigned long long aa = pack2(a, a);
                    a2[rr][0] = ffma2(aa, (unsigned long long)B0.x, a2[rr][0]);
                    a2[rr][1] = ffma2(aa, (unsigned long long)B0.y, a2[rr][1]);
                    a2[rr][2] = ffma2(aa, (unsigned long long)B1.x, a2[rr][2]);
                    a2[rr][3] = ffma2(aa, (unsigned long long)B1.y, a2[rr][3]);
                }
            }
#pragma unroll
            for (int rr = 0; rr < 8; ++rr) {
                int r = rg1 * 8 + rr;
                float2 p0 = unpack2(a2[rr][0]);
                float2 p1 = unpack2(a2[rr][1]);
                float2 p2 = unpack2(a2[rr][2]);
                float2 p3 = unpack2(a2[rr][3]);
                uint4 o;
                o.x = bf16x2_of(gelu_fast(p0.x + bc1s[cg1 * 8 + 0]),
                                gelu_fast(p0.y + bc1s[cg1 * 8 + 1]));
                o.y = bf16x2_of(gelu_fast(p1.x + bc1s[cg1 * 8 + 2]),
                                gelu_fast(p1.y + bc1s[cg1 * 8 + 3]));
                o.z = bf16x2_of(gelu_fast(p2.x + bc1s[cg1 * 8 + 4]),
                                gelu_fast(p2.y + bc1s[cg1 * 8 + 5]));
                o.w = bf16x2_of(gelu_fast(p3.x + bc1s[cg1 * 8 + 6]),
                                gelu_fast(p3.y + bc1s[cg1 * 8 + 7]));
                *reinterpret_cast<uint4*>(&T1b[r * STR1 + cg1 * 8]) = o;
            }
        }
        __syncthreads();

        float acc[2][8][4];

        // ---- stage 2 ----
#pragma unroll
        for (int mt = 0; mt < 2; ++mt)
#pragma unroll
            for (int i = 0; i < 8; ++i)
#pragma unroll
                for (int k = 0; k < 4; ++k) acc[mt][i][k] = 0.f;

#pragma unroll
        for (int s = 0; s < 8; ++s) {
            const unsigned kb = 32 * s;
            unsigned A[2][4];
            ldsm_x4(A[0][0], A[0][1], A[0][2], A[0][3], a1_base0 + kb);
            ldsm_x4(A[1][0], A[1][1], A[1][2], A[1][3], a1_base1 + kb);
#pragma unroll
            for (int ii = 0; ii < 4; ++ii) {
                unsigned r0, r1, r2, r3;
                ldsm_x4(r0, r1, r2, r3, b2_base[ii] + kb);
                mma16816(acc[0][2 * ii],     A[0], r0, r1);
                mma16816(acc[1][2 * ii],     A[1], r0, r1);
                mma16816(acc[0][2 * ii + 1], A[0], r2, r3);
                mma16816(acc[1][2 * ii + 1], A[1], r2, r3);
            }
        }

#pragma unroll
        for (int mt = 0; mt < 2; ++mt) {
#pragma unroll
            for (int i = 0; i < 8; ++i) {
                const int c0 = nc0 + 8 * i + 2 * ft;
                const int rlo = m0 + 16 * mt + fg;
                float2 bc = *reinterpret_cast<const float2*>(&bc2s[c0]);
                unsigned lo = bf16x2_of(gelu_fast(acc[mt][i][0] + bc.x),
                                        gelu_fast(acc[mt][i][1] + bc.y));
                unsigned hi = bf16x2_of(gelu_fast(acc[mt][i][2] + bc.x),
                                        gelu_fast(acc[mt][i][3] + bc.y));
                *reinterpret_cast<unsigned*>(&T2b[rlo * STR1 + c0]) = lo;
                *reinterpret_cast<unsigned*>(&T2b[(rlo + 8) * STR1 + c0]) = hi;
            }
        }
        __syncthreads();

        // ---- stage 3 ----
#pragma unroll
        for (int mt = 0; mt < 2; ++mt)
#pragma unroll
            for (int i = 0; i < 8; ++i)
#pragma unroll
                for (int k = 0; k < 4; ++k) acc[mt][i][k] = 0.f;

#pragma unroll
        for (int p = 0; p < 2; ++p) {
#pragma unroll
            for (int s = 0; s < 8; ++s) {
                const unsigned kb = 32 * s;
                unsigned A[2][4];
                ldsm_x4(A[0][0], A[0][1], A[0][2], A[0][3], a2_base0 + kb);
                ldsm_x4(A[1][0], A[1][1], A[1][2], A[1][3], a2_base1 + kb);
                if (p == 0) {
                    unsigned q0 = qb[node * 64 + 8 * s + ft];
                    unsigned q1 = qb[node * 64 + 8 * s + ft + 4];
#pragma unroll
                    for (int mt = 0; mt < 2; ++mt) {
                        A[mt][0] = mul_bf16x2(A[mt][0], q0);
                        A[mt][1] = mul_bf16x2(A[mt][1], q0);
                        A[mt][2] = mul_bf16x2(A[mt][2], q1);
                        A[mt][3] = mul_bf16x2(A[mt][3], q1);
                    }
                }
                const unsigned pk = p * 256 + kb;
#pragma unroll
                for (int ii = 0; ii < 4; ++ii) {
                    unsigned r0, r1, r2, r3;
                    ldsm_x4(r0, r1, r2, r3, b3_base[ii] + pk);
                    mma16816(acc[0][2 * ii],     A[0], r0, r1);
                    mma16816(acc[1][2 * ii],     A[1], r0, r1);
                    mma16816(acc[0][2 * ii + 1], A[0], r2, r3);
                    mma16816(acc[1][2 * ii + 1], A[1], r2, r3);
                }
            }
        }

        // ---- epilogue ----
        float rs0[2] = {0.f, 0.f};
        float rs1[2] = {0.f, 0.f};
#pragma unroll
        for (int mt = 0; mt < 2; ++mt) {
#pragma unroll
            for (int i = 0; i < 8; ++i) {
                const int c0 = nc0 + 8 * i + 2 * ft;
                float2 b1 = *reinterpret_cast<const float2*>(&bs1s[c0]);
                float2 w2 = *reinterpret_cast<const float2*>(&Ws2s[c0]);
                rs0[mt] += gelu_fast(acc[mt][i][0] + b1.x) * w2.x
                         + gelu_fast(acc[mt][i][1] + b1.y) * w2.y;
                rs1[mt] += gelu_fast(acc[mt][i][2] + b1.x) * w2.x
                         + gelu_fast(acc[mt][i][3] + b1.y) * w2.y;
            }
        }
#pragma unroll
        for (int off = 1; off <= 2; off <<= 1) {
#pragma unroll
            for (int mt = 0; mt < 2; ++mt) {
                rs0[mt] += __shfl_xor_sync(0xffffffffu, rs0[mt], off);
                rs1[mt] += __shfl_xor_sync(0xffffffffu, rs1[mt], off);
            }
        }
        if (ft == 0) {
#pragma unroll
            for (int mt = 0; mt < 2; ++mt) {
                part[(m0 + 16 * mt + fg) * 2 + wn]     = rs0[mt];
                part[(m0 + 16 * mt + 8 + fg) * 2 + wn] = rs1[mt];
            }
        }
        __syncthreads();

        if (tid < 128) {
            const int r = tid;
            const int l = r >> 6, c = r & 63;
            const float* cfr = &cf_s[r * 10];
            float bias = 20.0f * cfr[0] + 4.0f * cfr[4] + 1.5f * cfr[5]
                       + 1.5f * cfr[1] - 1.5f * cfr[2] + 1.2f * cfr[6]
                       + 2.5f * cfr[7] + 1.6f * cfr[8] + 1.2f * cfr[9];
            float logit = part[2 * r] + part[2 * r + 1] + bs2v + bias;
            float amv = am_s[r];
            bool valid = (amv > 0.f) || (c == 0 && misc[l] > 0.5f);
            out[(size_t)(n0 + l) * 64 + c] = valid ? logit : NEGV;
        }
    }
}

// =========================================================================
extern "C" void kernel_launch(void* const* d_in, const int* in_sizes, int n_in,
                              void* d_out, int out_size) {
    const float* x    = (const float*)d_in[0];
    const float* cf   = (const float*)d_in[1];
    const int*   adj  = (const int*)  d_in[2];
    const float* am   = (const float*)d_in[3];
    const float* W1   = (const float*)d_in[4];
    const float* a1s  = (const float*)d_in[5];
    const float* a1d  = (const float*)d_in[6];
    const float* W2   = (const float*)d_in[7];
    const float* a2s  = (const float*)d_in[8];
    const float* a2d  = (const float*)d_in[9];
    const float* lnw  = (const float*)d_in[10];
    const float* lnb  = (const float*)d_in[11];
    const float* Wc1  = (const float*)d_in[12];
    const float* bc1  = (const float*)d_in[13];
    const float* Wc2  = (const float*)d_in[14];
    const float* bc2  = (const float*)d_in[15];
    const float* Wq   = (const float*)d_in[16];
    const float* bq   = (const float*)d_in[17];
    const float* Ws1  = (const float*)d_in[18];
    const float* bs1  = (const float*)d_in[19];
    const float* Ws2  = (const float*)d_in[20];
    const float* bs2  = (const float*)d_in[21];
    float* out = (float*)d_out;

    float *s1, *d1, *g1, *s2, *d2, *hn, *pt, *zp;
    unsigned *h1b, *h2b, *qbg;
    int* cnt;
    cudaGetSymbolAddress((void**)&s1, g_s1);
    cudaGetSymbolAddress((void**)&d1, g_d1);
    cudaGetSymbolAddress((void**)&g1, g_g1);
    cudaGetSymbolAddress((void**)&s2, g_s2);
    cudaGetSymbolAddress((void**)&d2, g_d2);
    cudaGetSymbolAddress((void**)&hn, g_hn);
    cudaGetSymbolAddress((void**)&h1b, g_h1b);
    cudaGetSymbolAddress((void**)&h2b, g_h2b);
    cudaGetSymbolAddress((void**)&qbg, g_qb);
    cudaGetSymbolAddress((void**)&pt, g_part);
    cudaGetSymbolAddress((void**)&zp, g_zp);
    cudaGetSymbolAddress((void**)&cnt, g_cnt);

    const int smem_k64  = (16 * 64  + WT_STR * 64)  * 4;
    const int smem_k128 = (16 * 128 + WT_STR * 128) * 4;

    cudaFuncSetAttribute(gemm_attn_kernel,
                         cudaFuncAttributeMaxDynamicSharedMemorySize, smem_k128);
    cudaFuncSetAttribute(cand_kernel,
                         cudaFuncAttributeMaxDynamicSharedMemorySize, CAND_SMEM_BYTES);

    dim3 gat_grid(128, GAT_SPLITS);

    // layer 1
    gemm_attn_kernel<<<256, 256, smem_k64>>>(x, 64, W1, a1s, a1d, nullptr,
                                             h1b, s1, d1);
    gat_part_kernel<<<gat_grid, 256>>>(h1b, s1, d1, adj, pt, zp,
                                       nullptr, nullptr, nullptr, g1, 0, cnt);
    // layer 2 + residual + LN
    gemm_attn_kernel<<<256, 256, smem_k128>>>(g1, 128, W2, a2s, a2d, nullptr,
                                              h2b, s2, d2);
    gat_part_kernel<<<gat_grid, 256>>>(h2b, s2, d2, adj, pt, zp,
                                       g1, lnw, lnb, hn, 1, cnt);
    // q projection -> packed bf16
    gemm_attn_kernel<<<256, 256, smem_k128>>>(hn, 128, Wq, nullptr, nullptr, bq,
                                              qbg, nullptr, nullptr);
    // persistent fused candidate head
    cand_kernel<<<148, 256, CAND_SMEM_BYTES>>>(cf, am, Wc1, bc1, Wc2, bc2,
                                               Ws1, bs1, Ws2, bs2, qbg, out);
}

// round 12
// speedup vs baseline: 1.4084x; 1.4084x over previous
#include <cuda_runtime.h>
#include <cuda_bf16.h>
#include <math.h>

#define N_NODES 4096
#define H_DIM   128
#define NEGV    (-1000000000.0f)
#define GAT_SPLITS 16
#define J_PER_SPLIT (N_NODES / GAT_SPLITS)   // 256 -> 8 tiles of 32
#define WT_STR 132
#define ADJ_WORDS (N_NODES / 32)             // 128 words per row

// ---------------- device scratch (no allocations allowed) ----------------
__device__ float g_s1[N_NODES];
__device__ float g_d1[N_NODES];
__device__ float g_g1[N_NODES * H_DIM];
__device__ float g_s2[N_NODES];
__device__ float g_d2[N_NODES];
__device__ float g_hn[N_NODES * H_DIM];
__device__ unsigned g_h1b[N_NODES * H_DIM / 2];   // bf16x2 packed h1
__device__ unsigned g_h2b[N_NODES * H_DIM / 2];   // bf16x2 packed h2
__device__ unsigned g_qb [N_NODES * H_DIM / 2];   // bf16x2 packed q
__device__ unsigned g_adjp[N_NODES * ADJ_WORDS];  // bit-packed adjacency (2MB)
__device__ float g_part[GAT_SPLITS * N_NODES * H_DIM];
__device__ float g_zp [GAT_SPLITS * N_NODES];

// ---- fast gelu: tanh-approx via MUFU.TANH ----
__device__ __forceinline__ float tanh_fast(float y) {
    float r;
    asm("tanh.approx.f32 %0, %1;" : "=f"(r) : "f"(y));
    return r;
}
__device__ __forceinline__ float gelu_fast(float x) {
    float x2 = x * x;
    float inner = x * fmaf(0.0356774081f, x2, 0.79788456080f);
    float hx = 0.5f * x;
    return fmaf(hx, tanh_fast(inner), hx);
}

// ---- packed fp32x2 FMA ----
__device__ __forceinline__ unsigned long long ffma2(unsigned long long a,
                                                    unsigned long long b,
                                                    unsigned long long c) {
    unsigned long long d;
    asm("fma.rn.f32x2 %0, %1, %2, %3;" : "=l"(d) : "l"(a), "l"(b), "l"(c));
    return d;
}
__device__ __forceinline__ unsigned long long pack2(float x, float y) {
    unsigned long long d;
    asm("mov.b64 %0, {%1, %2};" : "=l"(d) : "f"(x), "f"(y));
    return d;
}
__device__ __forceinline__ float2 unpack2(unsigned long long v) {
    float2 r;
    asm("mov.b64 {%0, %1}, %2;" : "=f"(r.x), "=f"(r.y) : "l"(v));
    return r;
}

// ---- bf16 helpers ----
__device__ __forceinline__ unsigned bf16x2_of(float lo, float hi) {
    unsigned r;
    asm("cvt.rn.bf16x2.f32 %0, %1, %2;" : "=r"(r) : "f"(hi), "f"(lo));
    return r;
}
__device__ __forceinline__ unsigned mul_bf16x2(unsigned a, unsigned b) {
    unsigned r;
    asm("mul.bf16x2 %0, %1, %2;" : "=r"(r) : "r"(a), "r"(b));
    return r;
}
__device__ __forceinline__ void mma16816(float* c, const unsigned* a,
                                         unsigned b0, unsigned b1) {
    asm("mma.sync.aligned.m16n8k16.row.col.f32.bf16.bf16.f32 "
        "{%0,%1,%2,%3}, {%4,%5,%6,%7}, {%8,%9}, {%0,%1,%2,%3};"
        : "+f"(c[0]), "+f"(c[1]), "+f"(c[2]), "+f"(c[3])
        : "r"(a[0]), "r"(a[1]), "r"(a[2]), "r"(a[3]), "r"(b0), "r"(b1));
}
__device__ __forceinline__ void ldsm_x4_t(unsigned& r0, unsigned& r1,
                                          unsigned& r2, unsigned& r3,
                                          unsigned addr) {
    asm volatile("ldmatrix.sync.aligned.m8n8.x4.trans.shared.b16 "
                 "{%0,%1,%2,%3}, [%4];"
                 : "=r"(r0), "=r"(r1), "=r"(r2), "=r"(r3) : "r"(addr));
}
__device__ __forceinline__ void ldsm_x4(unsigned& r0, unsigned& r1,
                                        unsigned& r2, unsigned& r3,
                                        unsigned addr) {
    asm volatile("ldmatrix.sync.aligned.m8n8.x4.shared.b16 "
                 "{%0,%1,%2,%3}, [%4];"
                 : "=r"(r0), "=r"(r1), "=r"(r2), "=r"(r3) : "r"(addr));
}
__device__ __forceinline__ unsigned smem_u32(const void* p) {
    return (unsigned)__cvta_generic_to_shared(p);
}

// =========================================================================
// Adjacency bit-pack: packed[w] = ballot(adj[32w + lane] > 0). 64MB -> 2MB.
// =========================================================================
__global__ void adj_pack_kernel(const int* __restrict__ adj,
                                unsigned* __restrict__ packed) {
    const int lane = threadIdx.x & 31;
    const int gw = (blockIdx.x * blockDim.x + threadIdx.x) >> 5;
    const int nw = (gridDim.x * blockDim.x) >> 5;
    for (int widx = gw; widx < N_NODES * ADJ_WORDS; widx += nw) {
        int v = adj[(size_t)widx * 32 + lane];
        unsigned m = __ballot_sync(0xffffffffu, v > 0);
        if (lane == 0) packed[widx] = m;
    }
}

// =========================================================================
// GEMM: h = in[4096][K] @ W[128][K]^T (+bias) -> packed bf16 (R10 config)
// =========================================================================
__global__ void gemm_attn_kernel(const float* __restrict__ in, int K,
                                 const float* __restrict__ W,
                                 const float* __restrict__ a_s,
                                 const float* __restrict__ a_d,
                                 const float* __restrict__ bias,
                                 unsigned* __restrict__ out_bf,
                                 float* __restrict__ s_out,
                                 float* __restrict__ d_out) {
    extern __shared__ float sm[];
    float* in_s = sm;            // 32*K
    float* Wt   = sm + 32 * K;   // K rows of WT_STR
    const int tid = threadIdx.x;
    const int i0  = blockIdx.x * 32;

    {
        const float4* gin4 = reinterpret_cast<const float4*>(in + (size_t)i0 * K);
        float4* in4 = reinterpret_cast<float4*>(in_s);
        for (int idx = tid; idx < 8 * K; idx += 256) in4[idx] = gin4[idx];
    }
    for (int idx = tid; idx < 128 * K; idx += 256) {
        int c = idx / K, k = idx - c * K;
        Wt[k * WT_STR + c] = W[idx];
    }
    __syncthreads();

    const int rg = tid >> 5;
    const int lane = tid & 31;
    unsigned long long acc2[4][2];
#pragma unroll
    for (int r = 0; r < 4; ++r) { acc2[r][0] = 0ull; acc2[r][1] = 0ull; }

    for (int k = 0; k < K; ++k) {
        longlong2 B = *reinterpret_cast<const longlong2*>(&Wt[k * WT_STR + lane * 4]);
#pragma unroll
        for (int rr = 0; rr < 4; ++rr) {
            float a = in_s[(rg * 4 + rr) * K + k];
            unsigned long long aa = pack2(a, a);
            acc2[rr][0] = ffma2(aa, (unsigned long long)B.x, acc2[rr][0]);
            acc2[rr][1] = ffma2(aa, (unsigned long long)B.y, acc2[rr][1]);
        }
    }

    float acc[4][4];
#pragma unroll
    for (int rr = 0; rr < 4; ++rr) {
        float2 p0 = unpack2(acc2[rr][0]);
        float2 p1 = unpack2(acc2[rr][1]);
        acc[rr][0] = p0.x; acc[rr][1] = p0.y; acc[rr][2] = p1.x; acc[rr][3] = p1.y;
    }

#pragma unroll
    for (int rr = 0; rr < 4; ++rr) {
        int row = i0 + rg * 4 + rr;
        float v0 = acc[rr][0], v1 = acc[rr][1], v2 = acc[rr][2], v3 = acc[rr][3];
        if (bias) {
            v0 += bias[lane * 4 + 0];
            v1 += bias[lane * 4 + 1];
            v2 += bias[lane * 4 + 2];
            v3 += bias[lane * 4 + 3];
        }
        uint2 o;
        o.x = bf16x2_of(v0, v1);
        o.y = bf16x2_of(v2, v3);
        *reinterpret_cast<uint2*>(&out_bf[(size_t)row * 64 + lane * 2]) = o;
    }

    if (s_out) {
#pragma unroll
        for (int rr = 0; rr < 4; ++rr) {
            float sp = 0.f, dp = 0.f;
#pragma unroll
            for (int cc = 0; cc < 4; ++cc) {
                int c = lane * 4 + cc;
                sp += acc[rr][cc] * __ldg(&a_s[c]);
                dp += acc[rr][cc] * __ldg(&a_d[c]);
            }
#pragma unroll
            for (int off = 16; off; off >>= 1) {
                sp += __shfl_xor_sync(0xffffffffu, sp, off);
                dp += __shfl_xor_sync(0xffffffffu, dp, off);
            }
            if (lane == 0) {
                s_out[i0 + rg * 4 + rr] = sp;
                d_out[i0 + rg * 4 + rr] = dp;
            }
        }
    }
}

// =========================================================================
// GAT split-K partial: adjacency from 2MB L2-resident bitmask (broadcast
// u32 per row-tile) instead of 64MB DRAM int32 stream.
// =========================================================================
#define GB_H0 0
#define GB_H1 8704
#define GB_W0 17408
#define GB_W1 19968
#define GB_TOTAL 22528

__global__ void __launch_bounds__(256, 3)
gat_part_kernel(const unsigned* __restrict__ hb,
                const float* __restrict__ s,
                const float* __restrict__ d,
                const unsigned* __restrict__ adjp,
                float* __restrict__ part,
                float* __restrict__ zp) {
    __shared__ __align__(16) char smraw[GB_TOTAL];
    __nv_bfloat16* h_sb[2] = { (__nv_bfloat16*)(smraw + GB_H0),
                               (__nv_bfloat16*)(smraw + GB_H1) };
    __nv_bfloat16* w_sb[2] = { (__nv_bfloat16*)(smraw + GB_W0),
                               (__nv_bfloat16*)(smraw + GB_W1) };

    const int tid = threadIdx.x;
    const int i0  = blockIdx.x * 32;
    const int sz  = blockIdx.y;
    const int jb  = sz * J_PER_SPLIT;

    const int lane = tid & 31;
    const int w    = tid >> 5;
    const int rg   = w;
    const int wi   = tid >> 3;
    const int wj   = (tid & 7) * 4;
    const float si = s[i0 + wi];
    const unsigned* adjrow = &adjp[(size_t)(i0 + wi) * ADJ_WORDS];

    const int fg = lane >> 2, ft = lane & 3;
    const int m0 = (w & 1) * 16;
    const int n0 = (w >> 1) * 32;
    const int lm_ti = lane >> 3, lm_r = lane & 7;
    const int lm_off = ((lm_ti & 1) * 8 + lm_r) * 136 + (lm_ti >> 1) * 8;
    const unsigned hb_u32[2] = { smem_u32(h_sb[0]), smem_u32(h_sb[1]) };
    const int aw = (m0 + fg) * 40 + 2 * ft;

    float zacc = 0.f;
    float acc[4][4];
#pragma unroll
    for (int i = 0; i < 4; ++i)
#pragma unroll
        for (int k = 0; k < 4; ++k) acc[i][k] = 0.f;

    unsigned abits; float4 dv; uint2 hv0, hv1, hv2, hv3;

#define GAT_LOAD(J0)                                                          \
    do {                                                                      \
        abits = adjrow[(J0) >> 5];                                            \
        dv = *reinterpret_cast<const float4*>(&d[(J0) + wj]);                 \
        const uint2* h2p = reinterpret_cast<const uint2*>(hb);                \
        hv0 = h2p[(size_t)((J0) + rg +  0) * 32 + lane];                      \
        hv1 = h2p[(size_t)((J0) + rg +  8) * 32 + lane];                      \
        hv2 = h2p[(size_t)((J0) + rg + 16) * 32 + lane];                      \
        hv3 = h2p[(size_t)((J0) + rg + 24) * 32 + lane];                      \
    } while (0)

#define GAT_STORE(BUF)                                                        \
    do {                                                                      \
        float w0 = 0.f, w1 = 0.f, w2 = 0.f, w3 = 0.f;                         \
        if ((abits >> (wj + 0)) & 1u) { float e = si + dv.x; e = (e > 0.f) ? e : 0.2f * e; w0 = __expf(e); } \
        if ((abits >> (wj + 1)) & 1u) { float e = si + dv.y; e = (e > 0.f) ? e : 0.2f * e; w1 = __expf(e); } \
        if ((abits >> (wj + 2)) & 1u) { float e = si + dv.z; e = (e > 0.f) ? e : 0.2f * e; w2 = __expf(e); } \
        if ((abits >> (wj + 3)) & 1u) { float e = si + dv.w; e = (e > 0.f) ? e : 0.2f * e; w3 = __expf(e); } \
        zacc += (w0 + w1) + (w2 + w3);                                        \
        uint2 wp; wp.x = bf16x2_of(w0, w1); wp.y = bf16x2_of(w2, w3);         \
        *reinterpret_cast<uint2*>(&w_sb[BUF][wi * 40 + wj]) = wp;             \
        *reinterpret_cast<uint2*>(&h_sb[BUF][(rg +  0) * 136 + lane * 4]) = hv0; \
        *reinterpret_cast<uint2*>(&h_sb[BUF][(rg +  8) * 136 + lane * 4]) = hv1; \
        *reinterpret_cast<uint2*>(&h_sb[BUF][(rg + 16) * 136 + lane * 4]) = hv2; \
        *reinterpret_cast<uint2*>(&h_sb[BUF][(rg + 24) * 136 + lane * 4]) = hv3; \
    } while (0)

    GAT_LOAD(jb);
    GAT_STORE(0);
    __syncthreads();

    int buf = 0;
    const int NT = J_PER_SPLIT / 32;
    for (int t = 0; t < NT; ++t) {
        const int nxt = jb + (t + 1) * 32;
        if (t + 1 < NT) GAT_LOAD(nxt);

        const __nv_bfloat16* wb = w_sb[buf];
        const unsigned hbase = hb_u32[buf] + lm_off * 2;
#pragma unroll
        for (int sstep = 0; sstep < 2; ++sstep) {
            const int k0 = 16 * sstep;
            unsigned A[4];
            A[0] = *reinterpret_cast<const unsigned*>(&wb[aw + k0]);
            A[1] = *reinterpret_cast<const unsigned*>(&wb[aw + 320 + k0]);
            A[2] = *reinterpret_cast<const unsigned*>(&wb[aw + k0 + 8]);
            A[3] = *reinterpret_cast<const unsigned*>(&wb[aw + 320 + k0 + 8]);
#pragma unroll
            for (int p = 0; p < 2; ++p) {
                unsigned r0, r1, r2, r3;
                ldsm_x4_t(r0, r1, r2, r3,
                          hbase + (k0 * 136 + n0 + 16 * p) * 2);
                mma16816(acc[2 * p + 0], A, r0, r1);
                mma16816(acc[2 * p + 1], A, r2, r3);
            }
        }

        if (t + 1 < NT) GAT_STORE(buf ^ 1);
        __syncthreads();
        buf ^= 1;
    }
#undef GAT_LOAD
#undef GAT_STORE

    zacc += __shfl_xor_sync(0xffffffffu, zacc, 4);
    zacc += __shfl_xor_sync(0xffffffffu, zacc, 2);
    zacc += __shfl_xor_sync(0xffffffffu, zacc, 1);
    if ((tid & 7) == 0) zp[(size_t)sz * N_NODES + i0 + wi] = zacc;

    float* pb = &part[((size_t)sz * N_NODES + i0) * 128];
#pragma unroll
    for (int i = 0; i < 4; ++i) {
        const int col = n0 + 8 * i + 2 * ft;
        float2 lo; lo.x = acc[i][0]; lo.y = acc[i][1];
        float2 hi; hi.x = acc[i][2]; hi.y = acc[i][3];
        *reinterpret_cast<float2*>(&pb[(m0 + fg) * 128 + col])     = lo;
        *reinterpret_cast<float2*>(&pb[(m0 + 8 + fg) * 128 + col]) = hi;
    }
}

// =========================================================================
// GAT reduce (separate kernel — R10 config; the R11 fusion regressed)
// =========================================================================
__global__ void gat_reduce_kernel(const float* __restrict__ part,
                                  const float* __restrict__ zp,
                                  const float* __restrict__ res,
                                  const float* __restrict__ lnw,
                                  const float* __restrict__ lnb,
                                  float* __restrict__ out,
                                  int do_ln) {
    __shared__ float z_s[32];
    const int tid = threadIdx.x;
    const int i0  = blockIdx.x * 32;
    const int rg  = tid >> 5;
    const int lane = tid & 31;

    if (tid < 32) {
        float z = 0.f;
#pragma unroll
        for (int s = 0; s < GAT_SPLITS; ++s)
            z += zp[(size_t)s * N_NODES + i0 + tid];
        z_s[tid] = z;
    }
    __syncthreads();

#pragma unroll
    for (int rr = 0; rr < 4; ++rr) {
        const int lrow = rg * 4 + rr;
        const int row  = i0 + lrow;
        float4 a = make_float4(0.f, 0.f, 0.f, 0.f);
#pragma unroll
        for (int s = 0; s < GAT_SPLITS; ++s) {
            float4 p = *reinterpret_cast<const float4*>(
                &part[((size_t)s * N_NODES + row) * 128 + lane * 4]);
            a.x += p.x; a.y += p.y; a.z += p.z; a.w += p.w;
        }
        const float z = z_s[lrow];
        const float zinv = (z > 0.f) ? (1.0f / z) : 0.f;
        float v[4] = {a.x, a.y, a.z, a.w};
#pragma unroll
        for (int cc = 0; cc < 4; ++cc) {
            float t = fmaxf(v[cc] * zinv, 0.f);
            if (res) t += res[(size_t)row * 128 + lane * 4 + cc];
            v[cc] = t;
        }
        if (do_ln) {
            float sum = v[0] + v[1] + v[2] + v[3];
            float sq  = v[0]*v[0] + v[1]*v[1] + v[2]*v[2] + v[3]*v[3];
#pragma unroll
            for (int off = 16; off; off >>= 1) {
                sum += __shfl_xor_sync(0xffffffffu, sum, off);
                sq  += __shfl_xor_sync(0xffffffffu, sq,  off);
            }
            const float mu  = sum * (1.0f / 128.0f);
            const float var = sq  * (1.0f / 128.0f) - mu * mu;
            const float rs  = rsqrtf(var + 1e-5f);
#pragma unroll
            for (int cc = 0; cc < 4; ++cc) {
                int c = lane * 4 + cc;
                v[cc] = (v[cc] - mu) * rs * __ldg(&lnw[c]) + __ldg(&lnb[c]);
            }
        }
        float4 o; o.x = v[0]; o.y = v[1]; o.z = v[2]; o.w = v[3];
        *reinterpret_cast<float4*>(&out[(size_t)row * 128 + lane * 4]) = o;
    }
}

// =========================================================================
// Candidate head: persistent bf16 MMA (unchanged from R10)
// =========================================================================
#define STR1 136
#define STR3 264

#define OB_WC2  0
#define OB_WS1  34816
#define OB_T1   102400
#define OB_T2   137216
#define OB_WC1T 172032
#define OB_CF   177152
#define OB_QB   182272
#define OB_BC1  182784
#define OB_BC2  183296
#define OB_BS1  183808
#define OB_WS2  184320
#define OB_AM   184832
#define OB_PART 185344
#define OB_MISC 186368
#define CAND_SMEM_BYTES 186400
#define N_PAIRS 2048

__global__ void __launch_bounds__(256, 1)
cand_kernel(const float* __restrict__ cf,
            const float* __restrict__ am,
            const float* __restrict__ Wc1, const float* __restrict__ bc1,
            const float* __restrict__ Wc2, const float* __restrict__ bc2,
            const float* __restrict__ Ws1, const float* __restrict__ bs1,
            const float* __restrict__ Ws2, const float* __restrict__ bs2,
            const unsigned* __restrict__ qbg,
            float* __restrict__ out) {
    extern __shared__ char smc[];
    __nv_bfloat16* Wc2b = (__nv_bfloat16*)(smc + OB_WC2);
    __nv_bfloat16* Ws1b = (__nv_bfloat16*)(smc + OB_WS1);
    __nv_bfloat16* T1b  = (__nv_bfloat16*)(smc + OB_T1);
    __nv_bfloat16* T2b  = (__nv_bfloat16*)(smc + OB_T2);
    float* Wc1t = (float*)(smc + OB_WC1T);
    float* cf_s = (float*)(smc + OB_CF);
    unsigned* qb = (unsigned*)(smc + OB_QB);
    float* bc1s = (float*)(smc + OB_BC1);
    float* bc2s = (float*)(smc + OB_BC2);
    float* bs1s = (float*)(smc + OB_BS1);
    float* Ws2s = (float*)(smc + OB_WS2);
    float* am_s = (float*)(smc + OB_AM);
    float* part = (float*)(smc + OB_PART);
    float* misc = (float*)(smc + OB_MISC);

    const int tid = threadIdx.x;

    for (int i2 = tid; i2 < 8192; i2 += 256) {
        int n = i2 >> 6, kp = i2 & 63;
        float2 v = *reinterpret_cast<const float2*>(&Wc2[n * 128 + 2 * kp]);
        *reinterpret_cast<unsigned*>(&Wc2b[n * STR1 + 2 * kp]) = bf16x2_of(v.x, v.y);
    }
    for (int i2 = tid; i2 < 16384; i2 += 256) {
        int n = i2 >> 7, kp = i2 & 127;
        float2 v = *reinterpret_cast<const float2*>(&Ws1[n * 256 + 2 * kp]);
        *reinterpret_cast<unsigned*>(&Ws1b[n * STR3 + 2 * kp]) = bf16x2_of(v.x, v.y);
    }
    for (int idx = tid; idx < 1280; idx += 256) {
        int c = idx / 10, j = idx - c * 10;
        Wc1t[j * 128 + c] = Wc1[idx];
    }
    if (tid < 128) {
        bc1s[tid] = bc1[tid];
        bc2s[tid] = bc2[tid];
        bs1s[tid] = bs1[tid];
        Ws2s[tid] = Ws2[tid];
    }
    const float bs2v = __ldg(&bs2[0]);

    const int w    = tid >> 5;
    const int lane = tid & 31;
    const int fg   = lane >> 2;
    const int ft   = lane & 3;
    const int wm   = w & 3;
    const int wn   = w >> 2;
    const int m0   = wm * 32;
    const int nc0  = wn * 64;
    const int node = wm >> 1;
    const int rg1  = tid >> 4;
    const int cg1  = tid & 15;

    const int a_row  = ((lane >> 3) & 1) * 8 + (lane & 7);
    const int a_koff = (lane >> 4) * 8;
    const unsigned t1_u32 = smem_u32(T1b);
    const unsigned t2_u32 = smem_u32(T2b);
    const unsigned a1_base0 = t1_u32 + 2 * ((m0 + a_row) * STR1 + a_koff);
    const unsigned a1_base1 = t1_u32 + 2 * ((m0 + 16 + a_row) * STR1 + a_koff);
    const unsigned a2_base0 = t2_u32 + 2 * ((m0 + a_row) * STR1 + a_koff);
    const unsigned a2_base1 = t2_u32 + 2 * ((m0 + 16 + a_row) * STR1 + a_koff);
    const int b_m     = lane >> 3;
    const int b_iloc  = b_m >> 1;
    const int b_koff  = (b_m & 1) * 8;
    const int b_row   = lane & 7;
    const unsigned wc2_u32 = smem_u32(Wc2b);
    const unsigned ws1_u32 = smem_u32(Ws1b);
    unsigned b2_base[4], b3_base[4];
#pragma unroll
    for (int ii = 0; ii < 4; ++ii) {
        int nrow = nc0 + 8 * (2 * ii + b_iloc) + b_row;
        b2_base[ii] = wc2_u32 + 2 * (nrow * STR1 + b_koff);
        b3_base[ii] = ws1_u32 + 2 * (nrow * STR3 + b_koff);
    }

    for (int pr = blockIdx.x; pr < N_PAIRS; pr += gridDim.x) {
        const int n0  = pr * 2;
        const int base_row = n0 * 64;

        __syncthreads();

        for (int idx = tid; idx < 1280; idx += 256)
            cf_s[idx] = cf[(size_t)base_row * 10 + idx];
        if (tid < 128) {
            qb[tid] = qbg[(size_t)n0 * 64 + tid];
            am_s[tid] = am[base_row + tid];
        }
        __syncthreads();

        if (tid < 2) {
            float ssum = 0.f;
            for (int c = 0; c < 64; ++c) ssum += am_s[tid * 64 + c];
            misc[tid] = (ssum <= 0.f) ? 1.f : 0.f;
        }

        // ---- stage 1 ----
        {
            unsigned long long a2[8][4];
#pragma unroll
            for (int r = 0; r < 8; ++r)
#pragma unroll
                for (int c = 0; c < 4; ++c) a2[r][c] = 0ull;
#pragma unroll
            for (int j = 0; j < 10; ++j) {
                longlong2 B0 = *reinterpret_cast<const longlong2*>(&Wc1t[j * 128 + cg1 * 8]);
                longlong2 B1 = *reinterpret_cast<const longlong2*>(&Wc1t[j * 128 + cg1 * 8 + 4]);
#pragma unroll
                for (int rr = 0; rr < 8; ++rr) {
                    float a = cf_s[(rg1 * 8 + rr) * 10 + j];
                    unsigned long long aa = pack2(a, a);
                    a2[rr][0] = ffma2(aa, (unsigned long long)B0.x, a2[rr][0]);
                    a2[rr][1] = ffma2(aa, (unsigned long long)B0.y, a2[rr][1]);
                    a2[rr][2] = ffma2(aa, (unsigned long long)B1.x, a2[rr][2]);
                    a2[rr][3] = ffma2(aa, (unsigned long long)B1.y, a2[rr][3]);
                }
            }
#pragma unroll
            for (int rr = 0; rr < 8; ++rr) {
                int r = rg1 * 8 + rr;
                float2 p0 = unpack2(a2[rr][0]);
                float2 p1 = unpack2(a2[rr][1]);
                float2 p2 = unpack2(a2[rr][2]);
                float2 p3 = unpack2(a2[rr][3]);
                uint4 o;
                o.x = bf16x2_of(gelu_fast(p0.x + bc1s[cg1 * 8 + 0]),
                                gelu_fast(p0.y + bc1s[cg1 * 8 + 1]));
                o.y = bf16x2_of(gelu_fast(p1.x + bc1s[cg1 * 8 + 2]),
                                gelu_fast(p1.y + bc1s[cg1 * 8 + 3]));
                o.z = bf16x2_of(gelu_fast(p2.x + bc1s[cg1 * 8 + 4]),
                                gelu_fast(p2.y + bc1s[cg1 * 8 + 5]));
                o.w = bf16x2_of(gelu_fast(p3.x + bc1s[cg1 * 8 + 6]),
                                gelu_fast(p3.y + bc1s[cg1 * 8 + 7]));
                *reinterpret_cast<uint4*>(&T1b[r * STR1 + cg1 * 8]) = o;
            }
        }
        __syncthreads();

        float acc[2][8][4];

        // ---- stage 2 ----
#pragma unroll
        for (int mt = 0; mt < 2; ++mt)
#pragma unroll
            for (int i = 0; i < 8; ++i)
#pragma unroll
                for (int k = 0; k < 4; ++k) acc[mt][i][k] = 0.f;

#pragma unroll
        for (int s = 0; s < 8; ++s) {
            const unsigned kb = 32 * s;
            unsigned A[2][4];
            ldsm_x4(A[0][0], A[0][1], A[0][2], A[0][3], a1_base0 + kb);
            ldsm_x4(A[1][0], A[1][1], A[1][2], A[1][3], a1_base1 + kb);
#pragma unroll
            for (int ii = 0; ii < 4; ++ii) {
                unsigned r0, r1, r2, r3;
                ldsm_x4(r0, r1, r2, r3, b2_base[ii] + kb);
                mma16816(acc[0][2 * ii],     A[0], r0, r1);
                mma16816(acc[1][2 * ii],     A[1], r0, r1);
                mma16816(acc[0][2 * ii + 1], A[0], r2, r3);
                mma16816(acc[1][2 * ii + 1], A[1], r2, r3);
            }
        }

#pragma unroll
        for (int mt = 0; mt < 2; ++mt) {
#pragma unroll
            for (int i = 0; i < 8; ++i) {
                const int c0 = nc0 + 8 * i + 2 * ft;
                const int rlo = m0 + 16 * mt + fg;
                float2 bc = *reinterpret_cast<const float2*>(&bc2s[c0]);
                unsigned lo = bf16x2_of(gelu_fast(acc[mt][i][0] + bc.x),
                                        gelu_fast(acc[mt][i][1] + bc.y));
                unsigned hi = bf16x2_of(gelu_fast(acc[mt][i][2] + bc.x),
                                        gelu_fast(acc[mt][i][3] + bc.y));
                *reinterpret_cast<unsigned*>(&T2b[rlo * STR1 + c0]) = lo;
                *reinterpret_cast<unsigned*>(&T2b[(rlo + 8) * STR1 + c0]) = hi;
            }
        }
        __syncthreads();

        // ---- stage 3 ----
#pragma unroll
        for (int mt = 0; mt < 2; ++mt)
#pragma unroll
            for (int i = 0; i < 8; ++i)
#pragma unroll
                for (int k = 0; k < 4; ++k) acc[mt][i][k] = 0.f;

#pragma unroll
        for (int p = 0; p < 2; ++p) {
#pragma unroll
            for (int s = 0; s < 8; ++s) {
                const unsigned kb = 32 * s;
                unsigned A[2][4];
                ldsm_x4(A[0][0], A[0][1], A[0][2], A[0][3], a2_base0 + kb);
                ldsm_x4(A[1][0], A[1][1], A[1][2], A[1][3], a2_base1 + kb);
                if (p == 0) {
                    unsigned q0 = qb[node * 64 + 8 * s + ft];
                    unsigned q1 = qb[node * 64 + 8 * s + ft + 4];
#pragma unroll
                    for (int mt = 0; mt < 2; ++mt) {
                        A[mt][0] = mul_bf16x2(A[mt][0], q0);
                        A[mt][1] = mul_bf16x2(A[mt][1], q0);
                        A[mt][2] = mul_bf16x2(A[mt][2], q1);
                        A[mt][3] = mul_bf16x2(A[mt][3], q1);
                    }
                }
                const unsigned pk = p * 256 + kb;
#pragma unroll
                for (int ii = 0; ii < 4; ++ii) {
                    unsigned r0, r1, r2, r3;
                    ldsm_x4(r0, r1, r2, r3, b3_base[ii] + pk);
                    mma16816(acc[0][2 * ii],     A[0], r0, r1);
                    mma16816(acc[1][2 * ii],     A[1], r0, r1);
                    mma16816(acc[0][2 * ii + 1], A[0], r2, r3);
                    mma16816(acc[1][2 * ii + 1], A[1], r2, r3);
                }
            }
        }

        // ---- epilogue ----
        float rs0[2] = {0.f, 0.f};
        float rs1[2] = {0.f, 0.f};
#pragma unroll
        for (int mt = 0; mt < 2; ++mt) {
#pragma unroll
            for (int i = 0; i < 8; ++i) {
                const int c0 = nc0 + 8 * i + 2 * ft;
                float2 b1 = *reinterpret_cast<const float2*>(&bs1s[c0]);
                float2 w2 = *reinterpret_cast<const float2*>(&Ws2s[c0]);
                rs0[mt] += gelu_fast(acc[mt][i][0] + b1.x) * w2.x
                         + gelu_fast(acc[mt][i][1] + b1.y) * w2.y;
                rs1[mt] += gelu_fast(acc[mt][i][2] + b1.x) * w2.x
                         + gelu_fast(acc[mt][i][3] + b1.y) * w2.y;
            }
        }
#pragma unroll
        for (int off = 1; off <= 2; off <<= 1) {
#pragma unroll
            for (int mt = 0; mt < 2; ++mt) {
                rs0[mt] += __shfl_xor_sync(0xffffffffu, rs0[mt], off);
                rs1[mt] += __shfl_xor_sync(0xffffffffu, rs1[mt], off);
            }
        }
        if (ft == 0) {
#pragma unroll
            for (int mt = 0; mt < 2; ++mt) {
                part[(m0 + 16 * mt + fg) * 2 + wn]     = rs0[mt];
                part[(m0 + 16 * mt + 8 + fg) * 2 + wn] = rs1[mt];
            }
        }
        __syncthreads();

        if (tid < 128) {
            const int r = tid;
            const int l = r >> 6, c = r & 63;
            const float* cfr = &cf_s[r * 10];
            float bias = 20.0f * cfr[0] + 4.0f * cfr[4] + 1.5f * cfr[5]
                       + 1.5f * cfr[1] - 1.5f * cfr[2] + 1.2f * cfr[6]
                       + 2.5f * cfr[7] + 1.6f * cfr[8] + 1.2f * cfr[9];
            float logit = part[2 * r] + part[2 * r + 1] + bs2v + bias;
            float amv = am_s[r];
            bool valid = (amv > 0.f) || (c == 0 && misc[l] > 0.5f);
            out[(size_t)(n0 + l) * 64 + c] = valid ? logit : NEGV;
        }
    }
}

// =========================================================================
extern "C" void kernel_launch(void* const* d_in, const int* in_sizes, int n_in,
                              void* d_out, int out_size) {
    const float* x    = (const float*)d_in[0];
    const float* cf   = (const float*)d_in[1];
    const int*   adj  = (const int*)  d_in[2];
    const float* am   = (const float*)d_in[3];
    const float* W1   = (const float*)d_in[4];
    const float* a1s  = (const float*)d_in[5];
    const float* a1d  = (const float*)d_in[6];
    const float* W2   = (const float*)d_in[7];
    const float* a2s  = (const float*)d_in[8];
    const float* a2d  = (const float*)d_in[9];
    const float* lnw  = (const float*)d_in[10];
    const float* lnb  = (const float*)d_in[11];
    const float* Wc1  = (const float*)d_in[12];
    const float* bc1  = (const float*)d_in[13];
    const float* Wc2  = (const float*)d_in[14];
    const float* bc2  = (const float*)d_in[15];
    const float* Wq   = (const float*)d_in[16];
    const float* bq   = (const float*)d_in[17];
    const float* Ws1  = (const float*)d_in[18];
    const float* bs1  = (const float*)d_in[19];
    const float* Ws2  = (const float*)d_in[20];
    const float* bs2  = (const float*)d_in[21];
    float* out = (float*)d_out;

    float *s1, *d1, *g1, *s2, *d2, *hn, *pt, *zp;
    unsigned *h1b, *h2b, *qbg, *adjp;
    cudaGetSymbolAddress((void**)&s1, g_s1);
    cudaGetSymbolAddress((void**)&d1, g_d1);
    cudaGetSymbolAddress((void**)&g1, g_g1);
    cudaGetSymbolAddress((void**)&s2, g_s2);
    cudaGetSymbolAddress((void**)&d2, g_d2);
    cudaGetSymbolAddress((void**)&hn, g_hn);
    cudaGetSymbolAddress((void**)&h1b, g_h1b);
    cudaGetSymbolAddress((void**)&h2b, g_h2b);
    cudaGetSymbolAddress((void**)&qbg, g_qb);
    cudaGetSymbolAddress((void**)&adjp, g_adjp);
    cudaGetSymbolAddress((void**)&pt, g_part);
    cudaGetSymbolAddress((void**)&zp, g_zp);

    const int smem_k64  = (32 * 64  + WT_STR * 64)  * 4;
    const int smem_k128 = (32 * 128 + WT_STR * 128) * 4;

    cudaFuncSetAttribute(gemm_attn_kernel,
                         cudaFuncAttributeMaxDynamicSharedMemorySize, smem_k128);
    cudaFuncSetAttribute(cand_kernel,
                         cudaFuncAttributeMaxDynamicSharedMemorySize, CAND_SMEM_BYTES);

    dim3 gat_grid(128, GAT_SPLITS);

    // adjacency bitmask pack (64MB -> 2MB, L2-resident for both layers)
    adj_pack_kernel<<<1024, 256>>>(adj, adjp);

    // layer 1
    gemm_attn_kernel<<<128, 256, smem_k64>>>(x, 64, W1, a1s, a1d, nullptr,
                                             h1b, s1, d1);
    gat_part_kernel<<<gat_grid, 256>>>(h1b, s1, d1, adjp, pt, zp);
    gat_reduce_kernel<<<128, 256>>>(pt, zp, nullptr, nullptr, nullptr, g1, 0);
    // layer 2 + residual + LN
    gemm_attn_kernel<<<128, 256, smem_k128>>>(g1, 128, W2, a2s, a2d, nullptr,
                                              h2b, s2, d2);
    gat_part_kernel<<<gat_grid, 256>>>(h2b, s2, d2, adjp, pt, zp);
    gat_reduce_kernel<<<128, 256>>>(pt, zp, g1, lnw, lnb, hn, 1);
    // q projection -> packed bf16
    gemm_attn_kernel<<<128, 256, smem_k128>>>(hn, 128, Wq, nullptr, nullptr, bq,
                                              qbg, nullptr, nullptr);
    // persistent fused candidate head
    cand_kernel<<<148, 256, CAND_SMEM_BYTES>>>(cf, am, Wc1, bc1, Wc2, bc2,
                                               Ws1, bs1, Ws2, bs2, qbg, out);
}

// round 14
// speedup vs baseline: 1.6077x; 1.1415x over previous
#include <cuda_runtime.h>
#include <cuda_bf16.h>
#include <math.h>

#define N_NODES 4096
#define H_DIM   128
#define NEGV    (-1000000000.0f)
#define GAT_SPLITS 16
#define J_PER_SPLIT (N_NODES / GAT_SPLITS)   // 256 -> 8 tiles of 32
#define WT_STR 132

// ---------------- device scratch (no allocations allowed) ----------------
__device__ float g_s1[N_NODES];
__device__ float g_d1[N_NODES];
__device__ float g_g1[N_NODES * H_DIM];
__device__ float g_s2[N_NODES];
__device__ float g_d2[N_NODES];
__device__ float g_hn[N_NODES * H_DIM];
__device__ unsigned g_h1b[N_NODES * H_DIM / 2];   // bf16x2 packed h1
__device__ unsigned g_h2b[N_NODES * H_DIM / 2];   // bf16x2 packed h2
__device__ unsigned g_qb [N_NODES * H_DIM / 2];   // bf16x2 packed q
__device__ float g_part[GAT_SPLITS * N_NODES * H_DIM];
__device__ float g_zp [GAT_SPLITS * N_NODES];

// ---- fast gelu: tanh-approx via MUFU.TANH ----
__device__ __forceinline__ float tanh_fast(float y) {
    float r;
    asm("tanh.approx.f32 %0, %1;" : "=f"(r) : "f"(y));
    return r;
}
__device__ __forceinline__ float gelu_fast(float x) {
    float x2 = x * x;
    float inner = x * fmaf(0.0356774081f, x2, 0.79788456080f);
    float hx = 0.5f * x;
    return fmaf(hx, tanh_fast(inner), hx);
}

// ---- packed fp32x2 FMA ----
__device__ __forceinline__ unsigned long long ffma2(unsigned long long a,
                                                    unsigned long long b,
                                                    unsigned long long c) {
    unsigned long long d;
    asm("fma.rn.f32x2 %0, %1, %2, %3;" : "=l"(d) : "l"(a), "l"(b), "l"(c));
    return d;
}
__device__ __forceinline__ unsigned long long pack2(float x, float y) {
    unsigned long long d;
    asm("mov.b64 %0, {%1, %2};" : "=l"(d) : "f"(x), "f"(y));
    return d;
}
__device__ __forceinline__ float2 unpack2(unsigned long long v) {
    float2 r;
    asm("mov.b64 {%0, %1}, %2;" : "=f"(r.x), "=f"(r.y) : "l"(v));
    return r;
}

// ---- bf16 helpers ----
__device__ __forceinline__ unsigned bf16x2_of(float lo, float hi) {
    unsigned r;
    asm("cvt.rn.bf16x2.f32 %0, %1, %2;" : "=r"(r) : "f"(hi), "f"(lo));
    return r;
}
__device__ __forceinline__ unsigned mul_bf16x2(unsigned a, unsigned b) {
    unsigned r;
    asm("mul.bf16x2 %0, %1, %2;" : "=r"(r) : "r"(a), "r"(b));
    return r;
}
__device__ __forceinline__ void mma16816(float* c, const unsigned* a,
                                         unsigned b0, unsigned b1) {
    asm("mma.sync.aligned.m16n8k16.row.col.f32.bf16.bf16.f32 "
        "{%0,%1,%2,%3}, {%4,%5,%6,%7}, {%8,%9}, {%0,%1,%2,%3};"
        : "+f"(c[0]), "+f"(c[1]), "+f"(c[2]), "+f"(c[3])
        : "r"(a[0]), "r"(a[1]), "r"(a[2]), "r"(a[3]), "r"(b0), "r"(b1));
}
__device__ __forceinline__ void ldsm_x4_t(unsigned& r0, unsigned& r1,
                                          unsigned& r2, unsigned& r3,
                                          unsigned addr) {
    asm volatile("ldmatrix.sync.aligned.m8n8.x4.trans.shared.b16 "
                 "{%0,%1,%2,%3}, [%4];"
                 : "=r"(r0), "=r"(r1), "=r"(r2), "=r"(r3) : "r"(addr));
}
__device__ __forceinline__ void ldsm_x4(unsigned& r0, unsigned& r1,
                                        unsigned& r2, unsigned& r3,
                                        unsigned addr) {
    asm volatile("ldmatrix.sync.aligned.m8n8.x4.shared.b16 "
                 "{%0,%1,%2,%3}, [%4];"
                 : "=r"(r0), "=r"(r1), "=r"(r2), "=r"(r3) : "r"(addr));
}
__device__ __forceinline__ unsigned smem_u32(const void* p) {
    return (unsigned)__cvta_generic_to_shared(p);
}

// =========================================================================
// GEMM: h = in[4096][K] @ W[128][K]^T (+bias) -> packed bf16.
// K is COMPILE-TIME -> K-loop fully unrolled, LDS prefetched by ptxas.
// =========================================================================
template <int K>
__global__ void gemm_attn_kernel(const float* __restrict__ in,
                                 const float* __restrict__ W,
                                 const float* __restrict__ a_s,
                                 const float* __restrict__ a_d,
                                 const float* __restrict__ bias,
                                 unsigned* __restrict__ out_bf,
                                 float* __restrict__ s_out,
                                 float* __restrict__ d_out) {
    extern __shared__ float sm[];
    float* in_s = sm;            // 32*K
    float* Wt   = sm + 32 * K;   // K rows of WT_STR
    const int tid = threadIdx.x;
    const int i0  = blockIdx.x * 32;

    {
        const float4* gin4 = reinterpret_cast<const float4*>(in + (size_t)i0 * K);
        float4* in4 = reinterpret_cast<float4*>(in_s);
#pragma unroll
        for (int t = 0; t < 8 * K / 256; ++t) in4[tid + t * 256] = gin4[tid + t * 256];
    }
#pragma unroll
    for (int t = 0; t < K / 2; ++t) {      // 128*K elems / 256 threads
        int idx = tid + t * 256;
        int c = idx / K, k = idx - c * K;
        Wt[k * WT_STR + c] = W[idx];
    }
    __syncthreads();

    const int rg = tid >> 5;
    const int lane = tid & 31;
    unsigned long long acc2[4][2];
#pragma unroll
    for (int r = 0; r < 4; ++r) { acc2[r][0] = 0ull; acc2[r][1] = 0ull; }

#pragma unroll 8
    for (int k = 0; k < K; ++k) {
        longlong2 B = *reinterpret_cast<const longlong2*>(&Wt[k * WT_STR + lane * 4]);
#pragma unroll
        for (int rr = 0; rr < 4; ++rr) {
            float a = in_s[(rg * 4 + rr) * K + k];
            unsigned long long aa = pack2(a, a);
            acc2[rr][0] = ffma2(aa, (unsigned long long)B.x, acc2[rr][0]);
            acc2[rr][1] = ffma2(aa, (unsigned long long)B.y, acc2[rr][1]);
        }
    }

    float acc[4][4];
#pragma unroll
    for (int rr = 0; rr < 4; ++rr) {
        float2 p0 = unpack2(acc2[rr][0]);
        float2 p1 = unpack2(acc2[rr][1]);
        acc[rr][0] = p0.x; acc[rr][1] = p0.y; acc[rr][2] = p1.x; acc[rr][3] = p1.y;
    }

#pragma unroll
    for (int rr = 0; rr < 4; ++rr) {
        int row = i0 + rg * 4 + rr;
        float v0 = acc[rr][0], v1 = acc[rr][1], v2 = acc[rr][2], v3 = acc[rr][3];
        if (bias) {
            v0 += bias[lane * 4 + 0];
            v1 += bias[lane * 4 + 1];
            v2 += bias[lane * 4 + 2];
            v3 += bias[lane * 4 + 3];
        }
        uint2 o;
        o.x = bf16x2_of(v0, v1);
        o.y = bf16x2_of(v2, v3);
        *reinterpret_cast<uint2*>(&out_bf[(size_t)row * 64 + lane * 2]) = o;
    }

    if (s_out) {
#pragma unroll
        for (int rr = 0; rr < 4; ++rr) {
            float sp = 0.f, dp = 0.f;
#pragma unroll
            for (int cc = 0; cc < 4; ++cc) {
                int c = lane * 4 + cc;
                sp += acc[rr][cc] * __ldg(&a_s[c]);
                dp += acc[rr][cc] * __ldg(&a_d[c]);
            }
#pragma unroll
            for (int off = 16; off; off >>= 1) {
                sp += __shfl_xor_sync(0xffffffffu, sp, off);
                dp += __shfl_xor_sync(0xffffffffu, dp, off);
            }
            if (lane == 0) {
                s_out[i0 + rg * 4 + rr] = sp;
                d_out[i0 + rg * 4 + rr] = dp;
            }
        }
    }
}

// =========================================================================
// GAT split-K partial (R10 config: int4 adjacency, 16 splits)
// =========================================================================
#define GB_H0 0
#define GB_H1 8704
#define GB_W0 17408
#define GB_W1 19968
#define GB_TOTAL 22528

__global__ void __launch_bounds__(256, 3)
gat_part_kernel(const unsigned* __restrict__ hb,
                const float* __restrict__ s,
                const float* __restrict__ d,
                const int*   __restrict__ adj,
                float* __restrict__ part,
                float* __restrict__ zp) {
    __shared__ __align__(16) char smraw[GB_TOTAL];
    __nv_bfloat16* h_sb[2] = { (__nv_bfloat16*)(smraw + GB_H0),
                               (__nv_bfloat16*)(smraw + GB_H1) };
    __nv_bfloat16* w_sb[2] = { (__nv_bfloat16*)(smraw + GB_W0),
                               (__nv_bfloat16*)(smraw + GB_W1) };

    const int tid = threadIdx.x;
    const int i0  = blockIdx.x * 32;
    const int sz  = blockIdx.y;
    const int jb  = sz * J_PER_SPLIT;

    const int lane = tid & 31;
    const int w    = tid >> 5;
    const int rg   = w;
    const int wi   = tid >> 3;
    const int wj   = (tid & 7) * 4;
    const float si = s[i0 + wi];

    const int fg = lane >> 2, ft = lane & 3;
    const int m0 = (w & 1) * 16;
    const int n0 = (w >> 1) * 32;
    const int lm_ti = lane >> 3, lm_r = lane & 7;
    const int lm_off = ((lm_ti & 1) * 8 + lm_r) * 136 + (lm_ti >> 1) * 8;
    const unsigned hb_u32[2] = { smem_u32(h_sb[0]), smem_u32(h_sb[1]) };
    const int aw = (m0 + fg) * 40 + 2 * ft;

    float zacc = 0.f;
    float acc[4][4];
#pragma unroll
    for (int i = 0; i < 4; ++i)
#pragma unroll
        for (int k = 0; k < 4; ++k) acc[i][k] = 0.f;

    int4 av; float4 dv; uint2 hv0, hv1, hv2, hv3;

#define GAT_LOAD(J0)                                                          \
    do {                                                                      \
        av = *reinterpret_cast<const int4*>(                                  \
            &adj[(size_t)(i0 + wi) * N_NODES + (J0) + wj]);                   \
        dv = *reinterpret_cast<const float4*>(&d[(J0) + wj]);                 \
        const uint2* h2p = reinterpret_cast<const uint2*>(hb);                \
        hv0 = h2p[(size_t)((J0) + rg +  0) * 32 + lane];                      \
        hv1 = h2p[(size_t)((J0) + rg +  8) * 32 + lane];                      \
        hv2 = h2p[(size_t)((J0) + rg + 16) * 32 + lane];                      \
        hv3 = h2p[(size_t)((J0) + rg + 24) * 32 + lane];                      \
    } while (0)

#define GAT_STORE(BUF)                                                        \
    do {                                                                      \
        float w0 = 0.f, w1 = 0.f, w2 = 0.f, w3 = 0.f;                         \
        if (av.x > 0) { float e = si + dv.x; e = (e > 0.f) ? e : 0.2f * e; w0 = __expf(e); } \
        if (av.y > 0) { float e = si + dv.y; e = (e > 0.f) ? e : 0.2f * e; w1 = __expf(e); } \
        if (av.z > 0) { float e = si + dv.z; e = (e > 0.f) ? e : 0.2f * e; w2 = __expf(e); } \
        if (av.w > 0) { float e = si + dv.w; e = (e > 0.f) ? e : 0.2f * e; w3 = __expf(e); } \
        zacc += (w0 + w1) + (w2 + w3);                                        \
        uint2 wp; wp.x = bf16x2_of(w0, w1); wp.y = bf16x2_of(w2, w3);         \
        *reinterpret_cast<uint2*>(&w_sb[BUF][wi * 40 + wj]) = wp;             \
        *reinterpret_cast<uint2*>(&h_sb[BUF][(rg +  0) * 136 + lane * 4]) = hv0; \
        *reinterpret_cast<uint2*>(&h_sb[BUF][(rg +  8) * 136 + lane * 4]) = hv1; \
        *reinterpret_cast<uint2*>(&h_sb[BUF][(rg + 16) * 136 + lane * 4]) = hv2; \
        *reinterpret_cast<uint2*>(&h_sb[BUF][(rg + 24) * 136 + lane * 4]) = hv3; \
    } while (0)

    GAT_LOAD(jb);
    GAT_STORE(0);
    __syncthreads();

    int buf = 0;
    const int NT = J_PER_SPLIT / 32;
    for (int t = 0; t < NT; ++t) {
        const int nxt = jb + (t + 1) * 32;
        if (t + 1 < NT) GAT_LOAD(nxt);

        const __nv_bfloat16* wb = w_sb[buf];
        const unsigned hbase = hb_u32[buf] + lm_off * 2;
#pragma unroll
        for (int sstep = 0; sstep < 2; ++sstep) {
            const int k0 = 16 * sstep;
            unsigned A[4];
            A[0] = *reinterpret_cast<const unsigned*>(&wb[aw + k0]);
            A[1] = *reinterpret_cast<const unsigned*>(&wb[aw + 320 + k0]);
            A[2] = *reinterpret_cast<const unsigned*>(&wb[aw + k0 + 8]);
            A[3] = *reinterpret_cast<const unsigned*>(&wb[aw + 320 + k0 + 8]);
#pragma unroll
            for (int p = 0; p < 2; ++p) {
                unsigned r0, r1, r2, r3;
                ldsm_x4_t(r0, r1, r2, r3,
                          hbase + (k0 * 136 + n0 + 16 * p) * 2);
                mma16816(acc[2 * p + 0], A, r0, r1);
                mma16816(acc[2 * p + 1], A, r2, r3);
            }
        }

        if (t + 1 < NT) GAT_STORE(buf ^ 1);
        __syncthreads();
        buf ^= 1;
    }
#undef GAT_LOAD
#undef GAT_STORE

    zacc += __shfl_xor_sync(0xffffffffu, zacc, 4);
    zacc += __shfl_xor_sync(0xffffffffu, zacc, 2);
    zacc += __shfl_xor_sync(0xffffffffu, zacc, 1);
    if ((tid & 7) == 0) zp[(size_t)sz * N_NODES + i0 + wi] = zacc;

    float* pb = &part[((size_t)sz * N_NODES + i0) * 128];
#pragma unroll
    for (int i = 0; i < 4; ++i) {
        const int col = n0 + 8 * i + 2 * ft;
        float2 lo; lo.x = acc[i][0]; lo.y = acc[i][1];
        float2 hi; hi.x = acc[i][2]; hi.y = acc[i][3];
        *reinterpret_cast<float2*>(&pb[(m0 + fg) * 128 + col])     = lo;
        *reinterpret_cast<float2*>(&pb[(m0 + 8 + fg) * 128 + col]) = hi;
    }
}

// =========================================================================
// GAT reduce: grid 512, 8 rows/CTA (one warp per row) for memory parallelism
// =========================================================================
__global__ void gat_reduce_kernel(const float* __restrict__ part,
                                  const float* __restrict__ zp,
                                  const float* __restrict__ res,
                                  const float* __restrict__ lnw,
                                  const float* __restrict__ lnb,
                                  float* __restrict__ out,
                                  int do_ln) {
    __shared__ float z_s[8];
    const int tid = threadIdx.x;
    const int i0  = blockIdx.x * 8;
    const int rg  = tid >> 5;       // warp -> row
    const int lane = tid & 31;

    if (tid < 8) {
        float z = 0.f;
#pragma unroll
        for (int s = 0; s < GAT_SPLITS; ++s)
            z += zp[(size_t)s * N_NODES + i0 + tid];
        z_s[tid] = z;
    }
    __syncthreads();

    const int row = i0 + rg;
    float4 a = make_float4(0.f, 0.f, 0.f, 0.f);
#pragma unroll
    for (int s = 0; s < GAT_SPLITS; ++s) {
        float4 p = *reinterpret_cast<const float4*>(
            &part[((size_t)s * N_NODES + row) * 128 + lane * 4]);
        a.x += p.x; a.y += p.y; a.z += p.z; a.w += p.w;
    }
    const float z = z_s[rg];
    const float zinv = (z > 0.f) ? (1.0f / z) : 0.f;
    float v[4] = {a.x, a.y, a.z, a.w};
#pragma unroll
    for (int cc = 0; cc < 4; ++cc) {
        float t = fmaxf(v[cc] * zinv, 0.f);
        if (res) t += res[(size_t)row * 128 + lane * 4 + cc];
        v[cc] = t;
    }
    if (do_ln) {
        float sum = v[0] + v[1] + v[2] + v[3];
        float sq  = v[0]*v[0] + v[1]*v[1] + v[2]*v[2] + v[3]*v[3];
#pragma unroll
        for (int off = 16; off; off >>= 1) {
            sum += __shfl_xor_sync(0xffffffffu, sum, off);
            sq  += __shfl_xor_sync(0xffffffffu, sq,  off);
        }
        const float mu  = sum * (1.0f / 128.0f);
        const float var = sq  * (1.0f / 128.0f) - mu * mu;
        const float rs  = rsqrtf(var + 1e-5f);
#pragma unroll
        for (int cc = 0; cc < 4; ++cc) {
            int c = lane * 4 + cc;
            v[cc] = (v[cc] - mu) * rs * __ldg(&lnw[c]) + __ldg(&lnb[c]);
        }
    }
    float4 o; o.x = v[0]; o.y = v[1]; o.z = v[2]; o.w = v[3];
    *reinterpret_cast<float4*>(&out[(size_t)row * 128 + lane * 4]) = o;
}

// =========================================================================
// Candidate head: persistent bf16 MMA (unchanged from R10)
// =========================================================================
#define STR1 136
#define STR3 264

#define OB_WC2  0
#define OB_WS1  34816
#define OB_T1   102400
#define OB_T2   137216
#define OB_WC1T 172032
#define OB_CF   177152
#define OB_QB   182272
#define OB_BC1  182784
#define OB_BC2  183296
#define OB_BS1  183808
#define OB_WS2  184320
#define OB_AM   184832
#define OB_PART 185344
#define OB_MISC 186368
#define CAND_SMEM_BYTES 186400
#define N_PAIRS 2048

__global__ void __launch_bounds__(256, 1)
cand_kernel(const float* __restrict__ cf,
            const float* __restrict__ am,
            const float* __restrict__ Wc1, const float* __restrict__ bc1,
            const float* __restrict__ Wc2, const float* __restrict__ bc2,
            const float* __restrict__ Ws1, const float* __restrict__ bs1,
            const float* __restrict__ Ws2, const float* __restrict__ bs2,
            const unsigned* __restrict__ qbg,
            float* __restrict__ out) {
    extern __shared__ char smc[];
    __nv_bfloat16* Wc2b = (__nv_bfloat16*)(smc + OB_WC2);
    __nv_bfloat16* Ws1b = (__nv_bfloat16*)(smc + OB_WS1);
    __nv_bfloat16* T1b  = (__nv_bfloat16*)(smc + OB_T1);
    __nv_bfloat16* T2b  = (__nv_bfloat16*)(smc + OB_T2);
    float* Wc1t = (float*)(smc + OB_WC1T);
    float* cf_s = (float*)(smc + OB_CF);
    unsigned* qb = (unsigned*)(smc + OB_QB);
    float* bc1s = (float*)(smc + OB_BC1);
    float* bc2s = (float*)(smc + OB_BC2);
    float* bs1s = (float*)(smc + OB_BS1);
    float* Ws2s = (float*)(smc + OB_WS2);
    float* am_s = (float*)(smc + OB_AM);
    float* part = (float*)(smc + OB_PART);
    float* misc = (float*)(smc + OB_MISC);

    const int tid = threadIdx.x;

    for (int i2 = tid; i2 < 8192; i2 += 256) {
        int n = i2 >> 6, kp = i2 & 63;
        float2 v = *reinterpret_cast<const float2*>(&Wc2[n * 128 + 2 * kp]);
        *reinterpret_cast<unsigned*>(&Wc2b[n * STR1 + 2 * kp]) = bf16x2_of(v.x, v.y);
    }
    for (int i2 = tid; i2 < 16384; i2 += 256) {
        int n = i2 >> 7, kp = i2 & 127;
        float2 v = *reinterpret_cast<const float2*>(&Ws1[n * 256 + 2 * kp]);
        *reinterpret_cast<unsigned*>(&Ws1b[n * STR3 + 2 * kp]) = bf16x2_of(v.x, v.y);
    }
    for (int idx = tid; idx < 1280; idx += 256) {
        int c = idx / 10, j = idx - c * 10;
        Wc1t[j * 128 + c] = Wc1[idx];
    }
    if (tid < 128) {
        bc1s[tid] = bc1[tid];
        bc2s[tid] = bc2[tid];
        bs1s[tid] = bs1[tid];
        Ws2s[tid] = Ws2[tid];
    }
    const float bs2v = __ldg(&bs2[0]);

    const int w    = tid >> 5;
    const int lane = tid & 31;
    const int fg   = lane >> 2;
    const int ft   = lane & 3;
    const int wm   = w & 3;
    const int wn   = w >> 2;
    const int m0   = wm * 32;
    const int nc0  = wn * 64;
    const int node = wm >> 1;
    const int rg1  = tid >> 4;
    const int cg1  = tid & 15;

    const int a_row  = ((lane >> 3) & 1) * 8 + (lane & 7);
    const int a_koff = (lane >> 4) * 8;
    const unsigned t1_u32 = smem_u32(T1b);
    const unsigned t2_u32 = smem_u32(T2b);
    const unsigned a1_base0 = t1_u32 + 2 * ((m0 + a_row) * STR1 + a_koff);
    const unsigned a1_base1 = t1_u32 + 2 * ((m0 + 16 + a_row) * STR1 + a_koff);
    const unsigned a2_base0 = t2_u32 + 2 * ((m0 + a_row) * STR1 + a_koff);
    const unsigned a2_base1 = t2_u32 + 2 * ((m0 + 16 + a_row) * STR1 + a_koff);
    const int b_m     = lane >> 3;
    const int b_iloc  = b_m >> 1;
    const int b_koff  = (b_m & 1) * 8;
    const int b_row   = lane & 7;
    const unsigned wc2_u32 = smem_u32(Wc2b);
    const unsigned ws1_u32 = smem_u32(Ws1b);
    unsigned b2_base[4], b3_base[4];
#pragma unroll
    for (int ii = 0; ii < 4; ++ii) {
        int nrow = nc0 + 8 * (2 * ii + b_iloc) + b_row;
        b2_base[ii] = wc2_u32 + 2 * (nrow * STR1 + b_koff);
        b3_base[ii] = ws1_u32 + 2 * (nrow * STR3 + b_koff);
    }

    for (int pr = blockIdx.x; pr < N_PAIRS; pr += gridDim.x) {
        const int n0  = pr * 2;
        const int base_row = n0 * 64;

        __syncthreads();

        for (int idx = tid; idx < 1280; idx += 256)
            cf_s[idx] = cf[(size_t)base_row * 10 + idx];
        if (tid < 128) {
            qb[tid] = qbg[(size_t)n0 * 64 + tid];
            am_s[tid] = am[base_row + tid];
        }
        __syncthreads();

        if (tid < 2) {
            float ssum = 0.f;
            for (int c = 0; c < 64; ++c) ssum += am_s[tid * 64 + c];
            misc[tid] = (ssum <= 0.f) ? 1.f : 0.f;
        }

        // ---- stage 1 ----
        {
            unsigned long long a2[8][4];
#pragma unroll
            for (int r = 0; r < 8; ++r)
#pragma unroll
                for (int c = 0; c < 4; ++c) a2[r][c] = 0ull;
#pragma unroll
            for (int j = 0; j < 10; ++j) {
                longlong2 B0 = *reinterpret_cast<const longlong2*>(&Wc1t[j * 128 + cg1 * 8]);
                longlong2 B1 = *reinterpret_cast<const longlong2*>(&Wc1t[j * 128 + cg1 * 8 + 4]);
#pragma unroll
                for (int rr = 0; rr < 8; ++rr) {
                    float a = cf_s[(rg1 * 8 + rr) * 10 + j];
                    unsigned long long aa = pack2(a, a);
                    a2[rr][0] = ffma2(aa, (unsigned long long)B0.x, a2[rr][0]);
                    a2[rr][1] = ffma2(aa, (unsigned long long)B0.y, a2[rr][1]);
                    a2[rr][2] = ffma2(aa, (unsigned long long)B1.x, a2[rr][2]);
                    a2[rr][3] = ffma2(aa, (unsigned long long)B1.y, a2[rr][3]);
                }
            }
#pragma unroll
            for (int rr = 0; rr < 8; ++rr) {
                int r = rg1 * 8 + rr;
                float2 p0 = unpack2(a2[rr][0]);
                float2 p1 = unpack2(a2[rr][1]);
                float2 p2 = unpack2(a2[rr][2]);
                float2 p3 = unpack2(a2[rr][3]);
                uint4 o;
                o.x = bf16x2_of(gelu_fast(p0.x + bc1s[cg1 * 8 + 0]),
                                gelu_fast(p0.y + bc1s[cg1 * 8 + 1]));
                o.y = bf16x2_of(gelu_fast(p1.x + bc1s[cg1 * 8 + 2]),
                                gelu_fast(p1.y + bc1s[cg1 * 8 + 3]));
                o.z = bf16x2_of(gelu_fast(p2.x + bc1s[cg1 * 8 + 4]),
                                gelu_fast(p2.y + bc1s[cg1 * 8 + 5]));
                o.w = bf16x2_of(gelu_fast(p3.x + bc1s[cg1 * 8 + 6]),
                                gelu_fast(p3.y + bc1s[cg1 * 8 + 7]));
                *reinterpret_cast<uint4*>(&T1b[r * STR1 + cg1 * 8]) = o;
            }
        }
        __syncthreads();

        float acc[2][8][4];

        // ---- stage 2 ----
#pragma unroll
        for (int mt = 0; mt < 2; ++mt)
#pragma unroll
            for (int i = 0; i < 8; ++i)
#pragma unroll
                for (int k = 0; k < 4; ++k) acc[mt][i][k] = 0.f;

#pragma unroll
        for (int s = 0; s < 8; ++s) {
            const unsigned kb = 32 * s;
            unsigned A[2][4];
            ldsm_x4(A[0][0], A[0][1], A[0][2], A[0][3], a1_base0 + kb);
            ldsm_x4(A[1][0], A[1][1], A[1][2], A[1][3], a1_base1 + kb);
#pragma unroll
            for (int ii = 0; ii < 4; ++ii) {
                unsigned r0, r1, r2, r3;
                ldsm_x4(r0, r1, r2, r3, b2_base[ii] + kb);
                mma16816(acc[0][2 * ii],     A[0], r0, r1);
                mma16816(acc[1][2 * ii],     A[1], r0, r1);
                mma16816(acc[0][2 * ii + 1], A[0], r2, r3);
                mma16816(acc[1][2 * ii + 1], A[1], r2, r3);
            }
        }

#pragma unroll
        for (int mt = 0; mt < 2; ++mt) {
#pragma unroll
            for (int i = 0; i < 8; ++i) {
                const int c0 = nc0 + 8 * i + 2 * ft;
                const int rlo = m0 + 16 * mt + fg;
                float2 bc = *reinterpret_cast<const float2*>(&bc2s[c0]);
                unsigned lo = bf16x2_of(gelu_fast(acc[mt][i][0] + bc.x),
                                        gelu_fast(acc[mt][i][1] + bc.y));
                unsigned hi = bf16x2_of(gelu_fast(acc[mt][i][2] + bc.x),
                                        gelu_fast(acc[mt][i][3] + bc.y));
                *reinterpret_cast<unsigned*>(&T2b[rlo * STR1 + c0]) = lo;
                *reinterpret_cast<unsigned*>(&T2b[(rlo + 8) * STR1 + c0]) = hi;
            }
        }
        __syncthreads();

        // ---- stage 3 ----
#pragma unroll
        for (int mt = 0; mt < 2; ++mt)
#pragma unroll
            for (int i = 0; i < 8; ++i)
#pragma unroll
                for (int k = 0; k < 4; ++k) acc[mt][i][k] = 0.f;

#pragma unroll
        for (int p = 0; p < 2; ++p) {
#pragma unroll
            for (int s = 0; s < 8; ++s) {
                const unsigned kb = 32 * s;
                unsigned A[2][4];
                ldsm_x4(A[0][0], A[0][1], A[0][2], A[0][3], a2_base0 + kb);
                ldsm_x4(A[1][0], A[1][1], A[1][2], A[1][3], a2_base1 + kb);
                if (p == 0) {
                    unsigned q0 = qb[node * 64 + 8 * s + ft];
                    unsigned q1 = qb[node * 64 + 8 * s + ft + 4];
#pragma unroll
                    for (int mt = 0; mt < 2; ++mt) {
                        A[mt][0] = mul_bf16x2(A[mt][0], q0);
                        A[mt][1] = mul_bf16x2(A[mt][1], q0);
                        A[mt][2] = mul_bf16x2(A[mt][2], q1);
                        A[mt][3] = mul_bf16x2(A[mt][3], q1);
                    }
                }
                const unsigned pk = p * 256 + kb;
#pragma unroll
                for (int ii = 0; ii < 4; ++ii) {
                    unsigned r0, r1, r2, r3;
                    ldsm_x4(r0, r1, r2, r3, b3_base[ii] + pk);
                    mma16816(acc[0][2 * ii],     A[0], r0, r1);
                    mma16816(acc[1][2 * ii],     A[1], r0, r1);
                    mma16816(acc[0][2 * ii + 1], A[0], r2, r3);
                    mma16816(acc[1][2 * ii + 1], A[1], r2, r3);
                }
            }
        }

        // ---- epilogue ----
        float rs0[2] = {0.f, 0.f};
        float rs1[2] = {0.f, 0.f};
#pragma unroll
        for (int mt = 0; mt < 2; ++mt) {
#pragma unroll
            for (int i = 0; i < 8; ++i) {
                const int c0 = nc0 + 8 * i + 2 * ft;
                float2 b1 = *reinterpret_cast<const float2*>(&bs1s[c0]);
                float2 w2 = *reinterpret_cast<const float2*>(&Ws2s[c0]);
                rs0[mt] += gelu_fast(acc[mt][i][0] + b1.x) * w2.x
                         + gelu_fast(acc[mt][i][1] + b1.y) * w2.y;
                rs1[mt] += gelu_fast(acc[mt][i][2] + b1.x) * w2.x
                         + gelu_fast(acc[mt][i][3] + b1.y) * w2.y;
            }
        }
#pragma unroll
        for (int off = 1; off <= 2; off <<= 1) {
#pragma unroll
            for (int mt = 0; mt < 2; ++mt) {
                rs0[mt] += __shfl_xor_sync(0xffffffffu, rs0[mt], off);
                rs1[mt] += __shfl_xor_sync(0xffffffffu, rs1[mt], off);
            }
        }
        if (ft == 0) {
#pragma unroll
            for (int mt = 0; mt < 2; ++mt) {
                part[(m0 + 16 * mt + fg) * 2 + wn]     = rs0[mt];
                part[(m0 + 16 * mt + 8 + fg) * 2 + wn] = rs1[mt];
            }
        }
        __syncthreads();

        if (tid < 128) {
            const int r = tid;
            const int l = r >> 6, c = r & 63;
            const float* cfr = &cf_s[r * 10];
            float bias = 20.0f * cfr[0] + 4.0f * cfr[4] + 1.5f * cfr[5]
                       + 1.5f * cfr[1] - 1.5f * cfr[2] + 1.2f * cfr[6]
                       + 2.5f * cfr[7] + 1.6f * cfr[8] + 1.2f * cfr[9];
            float logit = part[2 * r] + part[2 * r + 1] + bs2v + bias;
            float amv = am_s[r];
            bool valid = (amv > 0.f) || (c == 0 && misc[l] > 0.5f);
            out[(size_t)(n0 + l) * 64 + c] = valid ? logit : NEGV;
        }
    }
}

// =========================================================================
extern "C" void kernel_launch(void* const* d_in, const int* in_sizes, int n_in,
                              void* d_out, int out_size) {
    const float* x    = (const float*)d_in[0];
    const float* cf   = (const float*)d_in[1];
    const int*   adj  = (const int*)  d_in[2];
    const float* am   = (const float*)d_in[3];
    const float* W1   = (const float*)d_in[4];
    const float* a1s  = (const float*)d_in[5];
    const float* a1d  = (const float*)d_in[6];
    const float* W2   = (const float*)d_in[7];
    const float* a2s  = (const float*)d_in[8];
    const float* a2d  = (const float*)d_in[9];
    const float* lnw  = (const float*)d_in[10];
    const float* lnb  = (const float*)d_in[11];
    const float* Wc1  = (const float*)d_in[12];
    const float* bc1  = (const float*)d_in[13];
    const float* Wc2  = (const float*)d_in[14];
    const float* bc2  = (const float*)d_in[15];
    const float* Wq   = (const float*)d_in[16];
    const float* bq   = (const float*)d_in[17];
    const float* Ws1  = (const float*)d_in[18];
    const float* bs1  = (const float*)d_in[19];
    const float* Ws2  = (const float*)d_in[20];
    const float* bs2  = (const float*)d_in[21];
    float* out = (float*)d_out;

    float *s1, *d1, *g1, *s2, *d2, *hn, *pt, *zp;
    unsigned *h1b, *h2b, *qbg;
    cudaGetSymbolAddress((void**)&s1, g_s1);
    cudaGetSymbolAddress((void**)&d1, g_d1);
    cudaGetSymbolAddress((void**)&g1, g_g1);
    cudaGetSymbolAddress((void**)&s2, g_s2);
    cudaGetSymbolAddress((void**)&d2, g_d2);
    cudaGetSymbolAddress((void**)&hn, g_hn);
    cudaGetSymbolAddress((void**)&h1b, g_h1b);
    cudaGetSymbolAddress((void**)&h2b, g_h2b);
    cudaGetSymbolAddress((void**)&qbg, g_qb);
    cudaGetSymbolAddress((void**)&pt, g_part);
    cudaGetSymbolAddress((void**)&zp, g_zp);

    const int smem_k64  = (32 * 64  + WT_STR * 64)  * 4;
    const int smem_k128 = (32 * 128 + WT_STR * 128) * 4;

    cudaFuncSetAttribute(gemm_attn_kernel<64>,
                         cudaFuncAttributeMaxDynamicSharedMemorySize, smem_k64);
    cudaFuncSetAttribute(gemm_attn_kernel<128>,
                         cudaFuncAttributeMaxDynamicSharedMemorySize, smem_k128);
    cudaFuncSetAttribute(cand_kernel,
                         cudaFuncAttributeMaxDynamicSharedMemorySize, CAND_SMEM_BYTES);

    dim3 gat_grid(128, GAT_SPLITS);

    // layer 1
    gemm_attn_kernel<64><<<128, 256, smem_k64>>>(x, W1, a1s, a1d, nullptr,
                                                 h1b, s1, d1);
    gat_part_kernel<<<gat_grid, 256>>>(h1b, s1, d1, adj, pt, zp);
    gat_reduce_kernel<<<512, 256>>>(pt, zp, nullptr, nullptr, nullptr, g1, 0);
    // layer 2 + residual + LN
    gemm_attn_kernel<128><<<128, 256, smem_k128>>>(g1, W2, a2s, a2d, nullptr,
                                                   h2b, s2, d2);
    gat_part_kernel<<<gat_grid, 256>>>(h2b, s2, d2, adj, pt, zp);
    gat_reduce_kernel<<<512, 256>>>(pt, zp, g1, lnw, lnb, hn, 1);
    // q projection -> packed bf16
    gemm_attn_kernel<128><<<128, 256, smem_k128>>>(hn, Wq, nullptr, nullptr, bq,
                                                   qbg, nullptr, nullptr);
    // persistent fused candidate head
    cand_kernel<<<148, 256, CAND_SMEM_BYTES>>>(cf, am, Wc1, bc1, Wc2, bc2,
                                               Ws1, bs1, Ws2, bs2, qbg, out);
}

// round 16
// speedup vs baseline: 1.8843x; 1.1720x over previous
#include <cuda_runtime.h>
#include <cuda_bf16.h>
#include <math.h>

#define N_NODES 4096
#define H_DIM   128
#define NEGV    (-1000000000.0f)
#define GAT_SPLITS 16
#define J_PER_SPLIT (N_NODES / GAT_SPLITS)   // 256 -> 8 tiles of 32
#define WT_STR 132

// ---------------- device scratch (no allocations allowed) ----------------
__device__ float g_s1[N_NODES];
__device__ float g_d1[N_NODES];
__device__ float g_g1[N_NODES * H_DIM];
__device__ float g_s2[N_NODES];
__device__ float g_d2[N_NODES];
__device__ float g_hn[N_NODES * H_DIM];
__device__ unsigned g_h1b[N_NODES * H_DIM / 2];   // bf16x2 packed h1
__device__ unsigned g_h2b[N_NODES * H_DIM / 2];   // bf16x2 packed h2
__device__ unsigned g_qb [N_NODES * H_DIM / 2];   // bf16x2 packed q
__device__ float g_part[GAT_SPLITS * N_NODES * H_DIM];
__device__ float g_zp [GAT_SPLITS * N_NODES];

// ---- fast gelu: tanh-approx via MUFU.TANH ----
__device__ __forceinline__ float tanh_fast(float y) {
    float r;
    asm("tanh.approx.f32 %0, %1;" : "=f"(r) : "f"(y));
    return r;
}
__device__ __forceinline__ float gelu_fast(float x) {
    float x2 = x * x;
    float inner = x * fmaf(0.0356774081f, x2, 0.79788456080f);
    float hx = 0.5f * x;
    return fmaf(hx, tanh_fast(inner), hx);
}

// ---- packed fp32x2 FMA ----
__device__ __forceinline__ unsigned long long ffma2(unsigned long long a,
                                                    unsigned long long b,
                                                    unsigned long long c) {
    unsigned long long d;
    asm("fma.rn.f32x2 %0, %1, %2, %3;" : "=l"(d) : "l"(a), "l"(b), "l"(c));
    return d;
}
__device__ __forceinline__ unsigned long long pack2(float x, float y) {
    unsigned long long d;
    asm("mov.b64 %0, {%1, %2};" : "=l"(d) : "f"(x), "f"(y));
    return d;
}
__device__ __forceinline__ float2 unpack2(unsigned long long v) {
    float2 r;
    asm("mov.b64 {%0, %1}, %2;" : "=f"(r.x), "=f"(r.y) : "l"(v));
    return r;
}

// ---- bf16 helpers ----
__device__ __forceinline__ unsigned bf16x2_of(float lo, float hi) {
    unsigned r;
    asm("cvt.rn.bf16x2.f32 %0, %1, %2;" : "=r"(r) : "f"(hi), "f"(lo));
    return r;
}
__device__ __forceinline__ unsigned mul_bf16x2(unsigned a, unsigned b) {
    unsigned r;
    asm("mul.bf16x2 %0, %1, %2;" : "=r"(r) : "r"(a), "r"(b));
    return r;
}
__device__ __forceinline__ void mma16816(float* c, const unsigned* a,
                                         unsigned b0, unsigned b1) {
    asm("mma.sync.aligned.m16n8k16.row.col.f32.bf16.bf16.f32 "
        "{%0,%1,%2,%3}, {%4,%5,%6,%7}, {%8,%9}, {%0,%1,%2,%3};"
        : "+f"(c[0]), "+f"(c[1]), "+f"(c[2]), "+f"(c[3])
        : "r"(a[0]), "r"(a[1]), "r"(a[2]), "r"(a[3]), "r"(b0), "r"(b1));
}
__device__ __forceinline__ void ldsm_x4_t(unsigned& r0, unsigned& r1,
                                          unsigned& r2, unsigned& r3,
                                          unsigned addr) {
    asm volatile("ldmatrix.sync.aligned.m8n8.x4.trans.shared.b16 "
                 "{%0,%1,%2,%3}, [%4];"
                 : "=r"(r0), "=r"(r1), "=r"(r2), "=r"(r3) : "r"(addr));
}
__device__ __forceinline__ void ldsm_x4(unsigned& r0, unsigned& r1,
                                        unsigned& r2, unsigned& r3,
                                        unsigned addr) {
    asm volatile("ldmatrix.sync.aligned.m8n8.x4.shared.b16 "
                 "{%0,%1,%2,%3}, [%4];"
                 : "=r"(r0), "=r"(r1), "=r"(r2), "=r"(r3) : "r"(addr));
}
__device__ __forceinline__ unsigned smem_u32(const void* p) {
    return (unsigned)__cvta_generic_to_shared(p);
}
// ---- cp.async ----
__device__ __forceinline__ void cp_async8(unsigned smem_addr, const void* gptr) {
    asm volatile("cp.async.ca.shared.global [%0], [%1], 8;"
                 :: "r"(smem_addr), "l"(gptr));
}
__device__ __forceinline__ void cp_commit() {
    asm volatile("cp.async.commit_group;");
}
template <int N> __device__ __forceinline__ void cp_wait() {
    asm volatile("cp.async.wait_group %0;" :: "n"(N));
}

// =========================================================================
// GEMM: h = in[4096][K] @ W[128][K]^T (+bias) -> packed bf16. (R14 config)
// =========================================================================
template <int K>
__global__ void gemm_attn_kernel(const float* __restrict__ in,
                                 const float* __restrict__ W,
                                 const float* __restrict__ a_s,
                                 const float* __restrict__ a_d,
                                 const float* __restrict__ bias,
                                 unsigned* __restrict__ out_bf,
                                 float* __restrict__ s_out,
                                 float* __restrict__ d_out) {
    extern __shared__ float sm[];
    float* in_s = sm;            // 32*K
    float* Wt   = sm + 32 * K;   // K rows of WT_STR
    const int tid = threadIdx.x;
    const int i0  = blockIdx.x * 32;

    {
        const float4* gin4 = reinterpret_cast<const float4*>(in + (size_t)i0 * K);
        float4* in4 = reinterpret_cast<float4*>(in_s);
#pragma unroll
        for (int t = 0; t < 8 * K / 256; ++t) in4[tid + t * 256] = gin4[tid + t * 256];
    }
#pragma unroll
    for (int t = 0; t < K / 2; ++t) {
        int idx = tid + t * 256;
        int c = idx / K, k = idx - c * K;
        Wt[k * WT_STR + c] = W[idx];
    }
    __syncthreads();

    const int rg = tid >> 5;
    const int lane = tid & 31;
    unsigned long long acc2[4][2];
#pragma unroll
    for (int r = 0; r < 4; ++r) { acc2[r][0] = 0ull; acc2[r][1] = 0ull; }

#pragma unroll 8
    for (int k = 0; k < K; ++k) {
        longlong2 B = *reinterpret_cast<const longlong2*>(&Wt[k * WT_STR + lane * 4]);
#pragma unroll
        for (int rr = 0; rr < 4; ++rr) {
            float a = in_s[(rg * 4 + rr) * K + k];
            unsigned long long aa = pack2(a, a);
            acc2[rr][0] = ffma2(aa, (unsigned long long)B.x, acc2[rr][0]);
            acc2[rr][1] = ffma2(aa, (unsigned long long)B.y, acc2[rr][1]);
        }
    }

    float acc[4][4];
#pragma unroll
    for (int rr = 0; rr < 4; ++rr) {
        float2 p0 = unpack2(acc2[rr][0]);
        float2 p1 = unpack2(acc2[rr][1]);
        acc[rr][0] = p0.x; acc[rr][1] = p0.y; acc[rr][2] = p1.x; acc[rr][3] = p1.y;
    }

#pragma unroll
    for (int rr = 0; rr < 4; ++rr) {
        int row = i0 + rg * 4 + rr;
        float v0 = acc[rr][0], v1 = acc[rr][1], v2 = acc[rr][2], v3 = acc[rr][3];
        if (bias) {
            v0 += bias[lane * 4 + 0];
            v1 += bias[lane * 4 + 1];
            v2 += bias[lane * 4 + 2];
            v3 += bias[lane * 4 + 3];
        }
        uint2 o;
        o.x = bf16x2_of(v0, v1);
        o.y = bf16x2_of(v2, v3);
        *reinterpret_cast<uint2*>(&out_bf[(size_t)row * 64 + lane * 2]) = o;
    }

    if (s_out) {
#pragma unroll
        for (int rr = 0; rr < 4; ++rr) {
            float sp = 0.f, dp = 0.f;
#pragma unroll
            for (int cc = 0; cc < 4; ++cc) {
                int c = lane * 4 + cc;
                sp += acc[rr][cc] * __ldg(&a_s[c]);
                dp += acc[rr][cc] * __ldg(&a_d[c]);
            }
#pragma unroll
            for (int off = 16; off; off >>= 1) {
                sp += __shfl_xor_sync(0xffffffffu, sp, off);
                dp += __shfl_xor_sync(0xffffffffu, dp, off);
            }
            if (lane == 0) {
                s_out[i0 + rg * 4 + rr] = sp;
                d_out[i0 + rg * 4 + rr] = dp;
            }
        }
    }
}

// =========================================================================
// GAT split-K partial: cp.async depth-2 pipeline for h tiles (3 buffers),
// register 1-tile lookahead for adjacency/d (weight generation).
// =========================================================================
#define GB_H0 0
#define GB_H1 8704
#define GB_H2 17408
#define GB_W0 26112
#define GB_W1 28672
#define GB_TOTAL 31232

__global__ void __launch_bounds__(256, 3)
gat_part_kernel(const unsigned* __restrict__ hb,
                const float* __restrict__ s,
                const float* __restrict__ d,
                const int*   __restrict__ adj,
                float* __restrict__ part,
                float* __restrict__ zp) {
    __shared__ __align__(16) char smraw[GB_TOTAL];
    __nv_bfloat16* h_sb[3] = { (__nv_bfloat16*)(smraw + GB_H0),
                               (__nv_bfloat16*)(smraw + GB_H1),
                               (__nv_bfloat16*)(smraw + GB_H2) };
    __nv_bfloat16* w_sb[2] = { (__nv_bfloat16*)(smraw + GB_W0),
                               (__nv_bfloat16*)(smraw + GB_W1) };

    const int tid = threadIdx.x;
    const int i0  = blockIdx.x * 32;
    const int sz  = blockIdx.y;
    const int jb  = sz * J_PER_SPLIT;

    const int lane = tid & 31;
    const int w    = tid >> 5;
    const int rg   = w;
    const int wi   = tid >> 3;
    const int wj   = (tid & 7) * 4;
    const float si = s[i0 + wi];

    const int fg = lane >> 2, ft = lane & 3;
    const int m0 = (w & 1) * 16;
    const int n0 = (w >> 1) * 32;
    const int lm_ti = lane >> 3, lm_r = lane & 7;
    const int lm_off = ((lm_ti & 1) * 8 + lm_r) * 136 + (lm_ti >> 1) * 8;
    const unsigned hb_u32[3] = { smem_u32(h_sb[0]), smem_u32(h_sb[1]),
                                 smem_u32(h_sb[2]) };
    const int aw = (m0 + fg) * 40 + 2 * ft;
    // per-thread cp.async dst offsets within an h buffer (bytes)
    const unsigned hd0 = (unsigned)(((rg +  0) * 136 + lane * 4) * 2);
    const unsigned hd1 = (unsigned)(((rg +  8) * 136 + lane * 4) * 2);
    const unsigned hd2 = (unsigned)(((rg + 16) * 136 + lane * 4) * 2);
    const unsigned hd3 = (unsigned)(((rg + 24) * 136 + lane * 4) * 2);

    float zacc = 0.f;
    float acc[4][4];
#pragma unroll
    for (int i = 0; i < 4; ++i)
#pragma unroll
        for (int k = 0; k < 4; ++k) acc[i][k] = 0.f;

    int4 av; float4 dv;

#define CP_H(T, BUF)                                                          \
    do {                                                                      \
        const int j0c = jb + (T) * 32;                                        \
        const unsigned sb = hb_u32[BUF];                                      \
        cp_async8(sb + hd0, hb + ((size_t)(j0c + rg +  0) * 64 + lane * 2));  \
        cp_async8(sb + hd1, hb + ((size_t)(j0c + rg +  8) * 64 + lane * 2));  \
        cp_async8(sb + hd2, hb + ((size_t)(j0c + rg + 16) * 64 + lane * 2));  \
        cp_async8(sb + hd3, hb + ((size_t)(j0c + rg + 24) * 64 + lane * 2));  \
    } while (0)

#define LDG_AD(T)                                                             \
    do {                                                                      \
        av = *reinterpret_cast<const int4*>(                                  \
            &adj[(size_t)(i0 + wi) * N_NODES + jb + (T) * 32 + wj]);          \
        dv = *reinterpret_cast<const float4*>(&d[jb + (T) * 32 + wj]);        \
    } while (0)

#define GEN_W(BUF)                                                            \
    do {                                                                      \
        float w0 = 0.f, w1 = 0.f, w2 = 0.f, w3 = 0.f;                         \
        if (av.x > 0) { float e = si + dv.x; e = (e > 0.f) ? e : 0.2f * e; w0 = __expf(e); } \
        if (av.y > 0) { float e = si + dv.y; e = (e > 0.f) ? e : 0.2f * e; w1 = __expf(e); } \
        if (av.z > 0) { float e = si + dv.z; e = (e > 0.f) ? e : 0.2f * e; w2 = __expf(e); } \
        if (av.w > 0) { float e = si + dv.w; e = (e > 0.f) ? e : 0.2f * e; w3 = __expf(e); } \
        zacc += (w0 + w1) + (w2 + w3);                                        \
        uint2 wp; wp.x = bf16x2_of(w0, w1); wp.y = bf16x2_of(w2, w3);         \
        *reinterpret_cast<uint2*>(&w_sb[BUF][wi * 40 + wj]) = wp;             \
    } while (0)

    const int NT = J_PER_SPLIT / 32;   // 8
    // prologue
    LDG_AD(0);
    CP_H(0, 0); cp_commit();
    CP_H(1, 1); cp_commit();
    GEN_W(0);
    LDG_AD(1);
    cp_wait<1>();          // h[0] resident
    __syncthreads();

    for (int t = 0; t < NT; ++t) {
        if (t + 2 < NT) CP_H(t + 2, (t + 2) % 3);
        cp_commit();       // uniform group counting (empty groups are legal)
        if (t + 1 < NT) GEN_W((t + 1) & 1);
        if (t + 2 < NT) LDG_AD(t + 2);

        const __nv_bfloat16* wb = w_sb[t & 1];
        const unsigned hbase = hb_u32[t % 3] + lm_off * 2;
#pragma unroll
        for (int sstep = 0; sstep < 2; ++sstep) {
            const int k0 = 16 * sstep;
            unsigned A[4];
            A[0] = *reinterpret_cast<const unsigned*>(&wb[aw + k0]);
            A[1] = *reinterpret_cast<const unsigned*>(&wb[aw + 320 + k0]);
            A[2] = *reinterpret_cast<const unsigned*>(&wb[aw + k0 + 8]);
            A[3] = *reinterpret_cast<const unsigned*>(&wb[aw + 320 + k0 + 8]);
#pragma unroll
            for (int p = 0; p < 2; ++p) {
                unsigned r0, r1, r2, r3;
                ldsm_x4_t(r0, r1, r2, r3,
                          hbase + (k0 * 136 + n0 + 16 * p) * 2);
                mma16816(acc[2 * p + 0], A, r0, r1);
                mma16816(acc[2 * p + 1], A, r2, r3);
            }
        }

        cp_wait<1>();      // h[t+1] resident before next iteration
        __syncthreads();
    }
#undef CP_H
#undef LDG_AD
#undef GEN_W

    zacc += __shfl_xor_sync(0xffffffffu, zacc, 4);
    zacc += __shfl_xor_sync(0xffffffffu, zacc, 2);
    zacc += __shfl_xor_sync(0xffffffffu, zacc, 1);
    if ((tid & 7) == 0) zp[(size_t)sz * N_NODES + i0 + wi] = zacc;

    float* pb = &part[((size_t)sz * N_NODES + i0) * 128];
#pragma unroll
    for (int i = 0; i < 4; ++i) {
        const int col = n0 + 8 * i + 2 * ft;
        float2 lo; lo.x = acc[i][0]; lo.y = acc[i][1];
        float2 hi; hi.x = acc[i][2]; hi.y = acc[i][3];
        *reinterpret_cast<float2*>(&pb[(m0 + fg) * 128 + col])     = lo;
        *reinterpret_cast<float2*>(&pb[(m0 + 8 + fg) * 128 + col]) = hi;
    }
}

// =========================================================================
// GAT reduce: grid 512, 8 rows/CTA (R14 config)
// =========================================================================
__global__ void gat_reduce_kernel(const float* __restrict__ part,
                                  const float* __restrict__ zp,
                                  const float* __restrict__ res,
                                  const float* __restrict__ lnw,
                                  const float* __restrict__ lnb,
                                  float* __restrict__ out,
                                  int do_ln) {
    __shared__ float z_s[8];
    const int tid = threadIdx.x;
    const int i0  = blockIdx.x * 8;
    const int rg  = tid >> 5;
    const int lane = tid & 31;

    if (tid < 8) {
        float z = 0.f;
#pragma unroll
        for (int s = 0; s < GAT_SPLITS; ++s)
            z += zp[(size_t)s * N_NODES + i0 + tid];
        z_s[tid] = z;
    }
    __syncthreads();

    const int row = i0 + rg;
    float4 a = make_float4(0.f, 0.f, 0.f, 0.f);
#pragma unroll
    for (int s = 0; s < GAT_SPLITS; ++s) {
        float4 p = *reinterpret_cast<const float4*>(
            &part[((size_t)s * N_NODES + row) * 128 + lane * 4]);
        a.x += p.x; a.y += p.y; a.z += p.z; a.w += p.w;
    }
    const float z = z_s[rg];
    const float zinv = (z > 0.f) ? (1.0f / z) : 0.f;
    float v[4] = {a.x, a.y, a.z, a.w};
#pragma unroll
    for (int cc = 0; cc < 4; ++cc) {
        float t = fmaxf(v[cc] * zinv, 0.f);
        if (res) t += res[(size_t)row * 128 + lane * 4 + cc];
        v[cc] = t;
    }
    if (do_ln) {
        float sum = v[0] + v[1] + v[2] + v[3];
        float sq  = v[0]*v[0] + v[1]*v[1] + v[2]*v[2] + v[3]*v[3];
#pragma unroll
        for (int off = 16; off; off >>= 1) {
            sum += __shfl_xor_sync(0xffffffffu, sum, off);
            sq  += __shfl_xor_sync(0xffffffffu, sq,  off);
        }
        const float mu  = sum * (1.0f / 128.0f);
        const float var = sq  * (1.0f / 128.0f) - mu * mu;
        const float rs  = rsqrtf(var + 1e-5f);
#pragma unroll
        for (int cc = 0; cc < 4; ++cc) {
            int c = lane * 4 + cc;
            v[cc] = (v[cc] - mu) * rs * __ldg(&lnw[c]) + __ldg(&lnb[c]);
        }
    }
    float4 o; o.x = v[0]; o.y = v[1]; o.z = v[2]; o.w = v[3];
    *reinterpret_cast<float4*>(&out[(size_t)row * 128 + lane * 4]) = o;
}

// =========================================================================
// Candidate head: persistent bf16 MMA + next-pair register prefetch
// =========================================================================
#define STR1 136
#define STR3 264

#define OB_WC2  0
#define OB_WS1  34816
#define OB_T1   102400
#define OB_T2   137216
#define OB_WC1T 172032
#define OB_CF   177152
#define OB_QB   182272
#define OB_BC1  182784
#define OB_BC2  183296
#define OB_BS1  183808
#define OB_WS2  184320
#define OB_AM   184832
#define OB_PART 185344
#define OB_MISC 186368
#define CAND_SMEM_BYTES 186400
#define N_PAIRS 2048

__global__ void __launch_bounds__(256, 1)
cand_kernel(const float* __restrict__ cf,
            const float* __restrict__ am,
            const float* __restrict__ Wc1, const float* __restrict__ bc1,
            const float* __restrict__ Wc2, const float* __restrict__ bc2,
            const float* __restrict__ Ws1, const float* __restrict__ bs1,
            const float* __restrict__ Ws2, const float* __restrict__ bs2,
            const unsigned* __restrict__ qbg,
            float* __restrict__ out) {
    extern __shared__ char smc[];
    __nv_bfloat16* Wc2b = (__nv_bfloat16*)(smc + OB_WC2);
    __nv_bfloat16* Ws1b = (__nv_bfloat16*)(smc + OB_WS1);
    __nv_bfloat16* T1b  = (__nv_bfloat16*)(smc + OB_T1);
    __nv_bfloat16* T2b  = (__nv_bfloat16*)(smc + OB_T2);
    float* Wc1t = (float*)(smc + OB_WC1T);
    float* cf_s = (float*)(smc + OB_CF);
    unsigned* qb = (unsigned*)(smc + OB_QB);
    float* bc1s = (float*)(smc + OB_BC1);
    float* bc2s = (float*)(smc + OB_BC2);
    float* bs1s = (float*)(smc + OB_BS1);
    float* Ws2s = (float*)(smc + OB_WS2);
    float* am_s = (float*)(smc + OB_AM);
    float* part = (float*)(smc + OB_PART);
    float* misc = (float*)(smc + OB_MISC);

    const int tid = threadIdx.x;

    for (int i2 = tid; i2 < 8192; i2 += 256) {
        int n = i2 >> 6, kp = i2 & 63;
        float2 v = *reinterpret_cast<const float2*>(&Wc2[n * 128 + 2 * kp]);
        *reinterpret_cast<unsigned*>(&Wc2b[n * STR1 + 2 * kp]) = bf16x2_of(v.x, v.y);
    }
    for (int i2 = tid; i2 < 16384; i2 += 256) {
        int n = i2 >> 7, kp = i2 & 127;
        float2 v = *reinterpret_cast<const float2*>(&Ws1[n * 256 + 2 * kp]);
        *reinterpret_cast<unsigned*>(&Ws1b[n * STR3 + 2 * kp]) = bf16x2_of(v.x, v.y);
    }
    for (int idx = tid; idx < 1280; idx += 256) {
        int c = idx / 10, j = idx - c * 10;
        Wc1t[j * 128 + c] = Wc1[idx];
    }
    if (tid < 128) {
        bc1s[tid] = bc1[tid];
        bc2s[tid] = bc2[tid];
        bs1s[tid] = bs1[tid];
        Ws2s[tid] = Ws2[tid];
    }
    const float bs2v = __ldg(&bs2[0]);

    const int w    = tid >> 5;
    const int lane = tid & 31;
    const int fg   = lane >> 2;
    const int ft   = lane & 3;
    const int wm   = w & 3;
    const int wn   = w >> 2;
    const int m0   = wm * 32;
    const int nc0  = wn * 64;
    const int node = wm >> 1;
    const int rg1  = tid >> 4;
    const int cg1  = tid & 15;

    const int a_row  = ((lane >> 3) & 1) * 8 + (lane & 7);
    const int a_koff = (lane >> 4) * 8;
    const unsigned t1_u32 = smem_u32(T1b);
    const unsigned t2_u32 = smem_u32(T2b);
    const unsigned a1_base0 = t1_u32 + 2 * ((m0 + a_row) * STR1 + a_koff);
    const unsigned a1_base1 = t1_u32 + 2 * ((m0 + 16 + a_row) * STR1 + a_koff);
    const unsigned a2_base0 = t2_u32 + 2 * ((m0 + a_row) * STR1 + a_koff);
    const unsigned a2_base1 = t2_u32 + 2 * ((m0 + 16 + a_row) * STR1 + a_koff);
    const int b_m     = lane >> 3;
    const int b_iloc  = b_m >> 1;
    const int b_koff  = (b_m & 1) * 8;
    const int b_row   = lane & 7;
    const unsigned wc2_u32 = smem_u32(Wc2b);
    const unsigned ws1_u32 = smem_u32(Ws1b);
    unsigned b2_base[4], b3_base[4];
#pragma unroll
    for (int ii = 0; ii < 4; ++ii) {
        int nrow = nc0 + 8 * (2 * ii + b_iloc) + b_row;
        b2_base[ii] = wc2_u32 + 2 * (nrow * STR1 + b_koff);
        b3_base[ii] = ws1_u32 + 2 * (nrow * STR3 + b_koff);
    }

    // ---- prefetch registers + first-pair load ----
    float cf_r[5];
    unsigned qb_r = 0u;
    float am_r = 0.f;
    {
        const int pr0 = blockIdx.x;           // < 2048 always
        const int b0 = pr0 * 128;
#pragma unroll
        for (int i = 0; i < 5; ++i)
            cf_r[i] = cf[(size_t)b0 * 10 + tid + i * 256];
        if (tid < 128) {
            qb_r = qbg[(size_t)pr0 * 128 + tid];
            am_r = am[b0 + tid];
        }
    }

    for (int pr = blockIdx.x; pr < N_PAIRS; pr += gridDim.x) {
        const int n0 = pr * 2;

        __syncthreads();
        // STS prefetched inputs (no LDG latency on the critical path)
#pragma unroll
        for (int i = 0; i < 5; ++i) cf_s[tid + i * 256] = cf_r[i];
        if (tid < 128) {
            qb[tid] = qb_r;
            am_s[tid] = am_r;
        }
        __syncthreads();

        if (tid < 2) {
            float ssum = 0.f;
            for (int c = 0; c < 64; ++c) ssum += am_s[tid * 64 + c];
            misc[tid] = (ssum <= 0.f) ? 1.f : 0.f;
        }

        // ---- stage 1 ----
        {
            unsigned long long a2[8][4];
#pragma unroll
            for (int r = 0; r < 8; ++r)
#pragma unroll
                for (int c = 0; c < 4; ++c) a2[r][c] = 0ull;
#pragma unroll
            for (int j = 0; j < 10; ++j) {
                longlong2 B0 = *reinterpret_cast<const longlong2*>(&Wc1t[j * 128 + cg1 * 8]);
                longlong2 B1 = *reinterpret_cast<const longlong2*>(&Wc1t[j * 128 + cg1 * 8 + 4]);
#pragma unroll
                for (int rr = 0; rr < 8; ++rr) {
                    float a = cf_s[(rg1 * 8 + rr) * 10 + j];
                    unsigned long long aa = pack2(a, a);
                    a2[rr][0] = ffma2(aa, (unsigned long long)B0.x, a2[rr][0]);
                    a2[rr][1] = ffma2(aa, (unsigned long long)B0.y, a2[rr][1]);
                    a2[rr][2] = ffma2(aa, (unsigned long long)B1.x, a2[rr][2]);
                    a2[rr][3] = ffma2(aa, (unsigned long long)B1.y, a2[rr][3]);
                }
            }
#pragma unroll
            for (int rr = 0; rr < 8; ++rr) {
                int r = rg1 * 8 + rr;
                float2 p0 = unpack2(a2[rr][0]);
                float2 p1 = unpack2(a2[rr][1]);
                float2 p2 = unpack2(a2[rr][2]);
                float2 p3 = unpack2(a2[rr][3]);
                uint4 o;
                o.x = bf16x2_of(gelu_fast(p0.x + bc1s[cg1 * 8 + 0]),
                                gelu_fast(p0.y + bc1s[cg1 * 8 + 1]));
                o.y = bf16x2_of(gelu_fast(p1.x + bc1s[cg1 * 8 + 2]),
                                gelu_fast(p1.y + bc1s[cg1 * 8 + 3]));
                o.z = bf16x2_of(gelu_fast(p2.x + bc1s[cg1 * 8 + 4]),
                                gelu_fast(p2.y + bc1s[cg1 * 8 + 5]));
                o.w = bf16x2_of(gelu_fast(p3.x + bc1s[cg1 * 8 + 6]),
                                gelu_fast(p3.y + bc1s[cg1 * 8 + 7]));
                *reinterpret_cast<uint4*>(&T1b[r * STR1 + cg1 * 8]) = o;
            }
        }
        __syncthreads();

        // ---- prefetch next pair's inputs (overlaps stages 2/3) ----
        {
            const int nxt = pr + gridDim.x;
            if (nxt < N_PAIRS) {
                const int bn = nxt * 128;
#pragma unroll
                for (int i = 0; i < 5; ++i)
                    cf_r[i] = cf[(size_t)bn * 10 + tid + i * 256];
                if (tid < 128) {
                    qb_r = qbg[(size_t)nxt * 128 + tid];
                    am_r = am[bn + tid];
                }
            }
        }

        float acc[2][8][4];

        // ---- stage 2 ----
#pragma unroll
        for (int mt = 0; mt < 2; ++mt)
#pragma unroll
            for (int i = 0; i < 8; ++i)
#pragma unroll
                for (int k = 0; k < 4; ++k) acc[mt][i][k] = 0.f;

#pragma unroll
        for (int s = 0; s < 8; ++s) {
            const unsigned kb = 32 * s;
            unsigned A[2][4];
            ldsm_x4(A[0][0], A[0][1], A[0][2], A[0][3], a1_base0 + kb);
            ldsm_x4(A[1][0], A[1][1], A[1][2], A[1][3], a1_base1 + kb);
#pragma unroll
            for (int ii = 0; ii < 4; ++ii) {
                unsigned r0, r1, r2, r3;
                ldsm_x4(r0, r1, r2, r3, b2_base[ii] + kb);
                mma16816(acc[0][2 * ii],     A[0], r0, r1);
                mma16816(acc[1][2 * ii],     A[1], r0, r1);
                mma16816(acc[0][2 * ii + 1], A[0], r2, r3);
                mma16816(acc[1][2 * ii + 1], A[1], r2, r3);
            }
        }

#pragma unroll
        for (int mt = 0; mt < 2; ++mt) {
#pragma unroll
            for (int i = 0; i < 8; ++i) {
                const int c0 = nc0 + 8 * i + 2 * ft;
                const int rlo = m0 + 16 * mt + fg;
                float2 bc = *reinterpret_cast<const float2*>(&bc2s[c0]);
                unsigned lo = bf16x2_of(gelu_fast(acc[mt][i][0] + bc.x),
                                        gelu_fast(acc[mt][i][1] + bc.y));
                unsigned hi = bf16x2_of(gelu_fast(acc[mt][i][2] + bc.x),
                                        gelu_fast(acc[mt][i][3] + bc.y));
                *reinterpret_cast<unsigned*>(&T2b[rlo * STR1 + c0]) = lo;
                *reinterpret_cast<unsigned*>(&T2b[(rlo + 8) * STR1 + c0]) = hi;
            }
        }
        __syncthreads();

        // ---- stage 3 ----
#pragma unroll
        for (int mt = 0; mt < 2; ++mt)
#pragma unroll
            for (int i = 0; i < 8; ++i)
#pragma unroll
                for (int k = 0; k < 4; ++k) acc[mt][i][k] = 0.f;

#pragma unroll
        for (int p = 0; p < 2; ++p) {
#pragma unroll
            for (int s = 0; s < 8; ++s) {
                const unsigned kb = 32 * s;
                unsigned A[2][4];
                ldsm_x4(A[0][0], A[0][1], A[0][2], A[0][3], a2_base0 + kb);
                ldsm_x4(A[1][0], A[1][1], A[1][2], A[1][3], a2_base1 + kb);
                if (p == 0) {
                    unsigned q0 = qb[node * 64 + 8 * s + ft];
                    unsigned q1 = qb[node * 64 + 8 * s + ft + 4];
#pragma unroll
                    for (int mt = 0; mt < 2; ++mt) {
                        A[mt][0] = mul_bf16x2(A[mt][0], q0);
                        A[mt][1] = mul_bf16x2(A[mt][1], q0);
                        A[mt][2] = mul_bf16x2(A[mt][2], q1);
                        A[mt][3] = mul_bf16x2(A[mt][3], q1);
                    }
                }
                const unsigned pk = p * 256 + kb;
#pragma unroll
                for (int ii = 0; ii < 4; ++ii) {
                    unsigned r0, r1, r2, r3;
                    ldsm_x4(r0, r1, r2, r3, b3_base[ii] + pk);
                    mma16816(acc[0][2 * ii],     A[0], r0, r1);
                    mma16816(acc[1][2 * ii],     A[1], r0, r1);
                    mma16816(acc[0][2 * ii + 1], A[0], r2, r3);
                    mma16816(acc[1][2 * ii + 1], A[1], r2, r3);
                }
            }
        }

        // ---- epilogue ----
        float rs0[2] = {0.f, 0.f};
        float rs1[2] = {0.f, 0.f};
#pragma unroll
        for (int mt = 0; mt < 2; ++mt) {
#pragma unroll
            for (int i = 0; i < 8; ++i) {
                const int c0 = nc0 + 8 * i + 2 * ft;
                float2 b1 = *reinterpret_cast<const float2*>(&bs1s[c0]);
                float2 w2 = *reinterpret_cast<const float2*>(&Ws2s[c0]);
                rs0[mt] += gelu_fast(acc[mt][i][0] + b1.x) * w2.x
                         + gelu_fast(acc[mt][i][1] + b1.y) * w2.y;
                rs1[mt] += gelu_fast(acc[mt][i][2] + b1.x) * w2.x
                         + gelu_fast(acc[mt][i][3] + b1.y) * w2.y;
            }
        }
#pragma unroll
        for (int off = 1; off <= 2; off <<= 1) {
#pragma unroll
            for (int mt = 0; mt < 2; ++mt) {
                rs0[mt] += __shfl_xor_sync(0xffffffffu, rs0[mt], off);
                rs1[mt] += __shfl_xor_sync(0xffffffffu, rs1[mt], off);
            }
        }
        if (ft == 0) {
#pragma unroll
            for (int mt = 0; mt < 2; ++mt) {
                part[(m0 + 16 * mt + fg) * 2 + wn]     = rs0[mt];
                part[(m0 + 16 * mt + 8 + fg) * 2 + wn] = rs1[mt];
            }
        }
        __syncthreads();

        if (tid < 128) {
            const int r = tid;
            const int l = r >> 6, c = r & 63;
            const float* cfr = &cf_s[r * 10];
            float bias = 20.0f * cfr[0] + 4.0f * cfr[4] + 1.5f * cfr[5]
                       + 1.5f * cfr[1] - 1.5f * cfr[2] + 1.2f * cfr[6]
                       + 2.5f * cfr[7] + 1.6f * cfr[8] + 1.2f * cfr[9];
            float logit = part[2 * r] + part[2 * r + 1] + bs2v + bias;
            float amv = am_s[r];
            bool valid = (amv > 0.f) || (c == 0 && misc[l] > 0.5f);
            out[(size_t)(n0 + l) * 64 + c] = valid ? logit : NEGV;
        }
    }
}

// =========================================================================
extern "C" void kernel_launch(void* const* d_in, const int* in_sizes, int n_in,
                              void* d_out, int out_size) {
    const float* x    = (const float*)d_in[0];
    const float* cf   = (const float*)d_in[1];
    const int*   adj  = (const int*)  d_in[2];
    const float* am   = (const float*)d_in[3];
    const float* W1   = (const float*)d_in[4];
    const float* a1s  = (const float*)d_in[5];
    const float* a1d  = (const float*)d_in[6];
    const float* W2   = (const float*)d_in[7];
    const float* a2s  = (const float*)d_in[8];
    const float* a2d  = (const float*)d_in[9];
    const float* lnw  = (const float*)d_in[10];
    const float* lnb  = (const float*)d_in[11];
    const float* Wc1  = (const float*)d_in[12];
    const float* bc1  = (const float*)d_in[13];
    const float* Wc2  = (const float*)d_in[14];
    const float* bc2  = (const float*)d_in[15];
    const float* Wq   = (const float*)d_in[16];
    const float* bq   = (const float*)d_in[17];
    const float* Ws1  = (const float*)d_in[18];
    const float* bs1  = (const float*)d_in[19];
    const float* Ws2  = (const float*)d_in[20];
    const float* bs2  = (const float*)d_in[21];
    float* out = (float*)d_out;

    float *s1, *d1, *g1, *s2, *d2, *hn, *pt, *zp;
    unsigned *h1b, *h2b, *qbg;
    cudaGetSymbolAddress((void**)&s1, g_s1);
    cudaGetSymbolAddress((void**)&d1, g_d1);
    cudaGetSymbolAddress((void**)&g1, g_g1);
    cudaGetSymbolAddress((void**)&s2, g_s2);
    cudaGetSymbolAddress((void**)&d2, g_d2);
    cudaGetSymbolAddress((void**)&hn, g_hn);
    cudaGetSymbolAddress((void**)&h1b, g_h1b);
    cudaGetSymbolAddress((void**)&h2b, g_h2b);
    cudaGetSymbolAddress((void**)&qbg, g_qb);
    cudaGetSymbolAddress((void**)&pt, g_part);
    cudaGetSymbolAddress((void**)&zp, g_zp);

    const int smem_k64  = (32 * 64  + WT_STR * 64)  * 4;
    const int smem_k128 = (32 * 128 + WT_STR * 128) * 4;

    cudaFuncSetAttribute(gemm_attn_kernel<64>,
                         cudaFuncAttributeMaxDynamicSharedMemorySize, smem_k64);
    cudaFuncSetAttribute(gemm_attn_kernel<128>,
                         cudaFuncAttributeMaxDynamicSharedMemorySize, smem_k128);
    cudaFuncSetAttribute(cand_kernel,
                         cudaFuncAttributeMaxDynamicSharedMemorySize, CAND_SMEM_BYTES);

    dim3 gat_grid(128, GAT_SPLITS);

    // layer 1
    gemm_attn_kernel<64><<<128, 256, smem_k64>>>(x, W1, a1s, a1d, nullptr,
                                                 h1b, s1, d1);
    gat_part_kernel<<<gat_grid, 256>>>(h1b, s1, d1, adj, pt, zp);
    gat_reduce_kernel<<<512, 256>>>(pt, zp, nullptr, nullptr, nullptr, g1, 0);
    // layer 2 + residual + LN
    gemm_attn_kernel<128><<<128, 256, smem_k128>>>(g1, W2, a2s, a2d, nullptr,
                                                   h2b, s2, d2);
    gat_part_kernel<<<gat_grid, 256>>>(h2b, s2, d2, adj, pt, zp);
    gat_reduce_kernel<<<512, 256>>>(pt, zp, g1, lnw, lnb, hn, 1);
    // q projection -> packed bf16
    gemm_attn_kernel<128><<<128, 256, smem_k128>>>(hn, Wq, nullptr, nullptr, bq,
                                                   qbg, nullptr, nullptr);
    // persistent fused candidate head
    cand_kernel<<<148, 256, CAND_SMEM_BYTES>>>(cf, am, Wc1, bc1, Wc2, bc2,
                                               Ws1, bs1, Ws2, bs2, qbg, out);
}